// round 9
// baseline (speedup 1.0000x reference)
#include <cuda_runtime.h>
#include <cuda_bf16.h>
#include <cstdint>

#define BB   2
#define SS   2048
#define DD   1024
#define HH   16
#define KVHn 4
#define HD   64
#define WIN  64
#define MM   (BB*SS)   // 4096

typedef unsigned long long ull;

// packed f32x2 helpers (attention kernel)
#define PACK2(d, x, y)  asm("mov.b64 %0, {%1, %2};" : "=l"(d) : "f"(x), "f"(y))
#define DUP2(d, x)      asm("mov.b64 %0, {%1, %1};" : "=l"(d) : "f"(x))
#define UNPACK2(lo, hi, d) asm("mov.b64 {%0, %1}, %2;" : "=f"(lo), "=f"(hi) : "l"(d))
#define FMA2(d, a, b)   asm("fma.rn.f32x2 %0, %1, %2, %0;" : "+l"(d) : "l"(a), "l"(b))
#define MUL2(d, a, b)   asm("mul.rn.f32x2 %0, %1, %2;" : "=l"(d) : "l"(a), "l"(b))
#define ADD2(d, a, b)   asm("add.rn.f32x2 %0, %1, %2;" : "=l"(d) : "l"(a), "l"(b))

__device__ __forceinline__ uint32_t smem_u32(const void* p) {
    uint32_t a;
    asm("{ .reg .u64 t; cvta.to.shared.u64 t, %1; cvt.u32.u64 %0, t; }"
        : "=r"(a) : "l"(p));
    return a;
}

// warp-level tensor core + async copy (all plain sm_80+ ISA, no arch suffix)
__device__ __forceinline__ void ldsm4(uint32_t* r, uint32_t addr) {
    asm volatile("ldmatrix.sync.aligned.m8n8.x4.shared.b16 {%0,%1,%2,%3}, [%4];"
                 : "=r"(r[0]), "=r"(r[1]), "=r"(r[2]), "=r"(r[3]) : "r"(addr));
}
__device__ __forceinline__ void mma_bf16(float* c, const uint32_t* a, const uint32_t* b) {
    asm volatile(
        "mma.sync.aligned.m16n8k16.row.col.f32.bf16.bf16.f32 "
        "{%0,%1,%2,%3}, {%4,%5,%6,%7}, {%8,%9}, {%0,%1,%2,%3};"
        : "+f"(c[0]), "+f"(c[1]), "+f"(c[2]), "+f"(c[3])
        : "r"(a[0]), "r"(a[1]), "r"(a[2]), "r"(a[3]), "r"(b[0]), "r"(b[1]));
}
#define CPA16(dst, src) \
    asm volatile("cp.async.cg.shared.global [%0], [%1], 16;" :: "r"(dst), "l"(src) : "memory")
#define CPA_COMMIT() asm volatile("cp.async.commit_group;" ::: "memory")
#define CPA_WAIT0()  asm volatile("cp.async.wait_group 0;" ::: "memory")

// swizzled byte offset within a [rows x 32B] smem array (16B-unit XOR):
// row r, 16B-half c -> r*32 + ((c ^ ((r>>2)&1))<<4). Conflict-free for
// ldmatrix (8 consecutive rows hit 8 distinct 16B slots) and invariant
// under r += 16 (so ldmatrix tile offsets are constant +512B strides).
__device__ __forceinline__ uint32_t swz(int r, int c) {
    return (uint32_t)(r * 32 + ((c ^ ((r >> 2) & 1)) << 4));
}

// ---------------------------------------------------------------------------
// Device scratch
// ---------------------------------------------------------------------------
__device__ float g_q[MM * HH * HD];
__device__ float g_k[MM * KVHn * HD];
__device__ float g_v[MM * KVHn * HD];
__device__ __nv_bfloat16 g_xhi[MM * DD],  g_xlo[MM * DD];          // x split
__device__ __nv_bfloat16 g_wt_hi[1536 * DD], g_wt_lo[1536 * DD];   // [wq|wk|wv]^T
__device__ __nv_bfloat16 g_wo_hi[DD * DD],   g_wo_lo[DD * DD];     // wo^T
__device__ __nv_bfloat16 g_ahi[MM * DD],  g_alo[MM * DD];          // attn out split

// ---------------------------------------------------------------------------
// Split fp32 -> bf16 hi/lo (no transpose). 4 elems/thread.
// ---------------------------------------------------------------------------
__global__ __launch_bounds__(256) void split_kernel(
    const float* __restrict__ src, __nv_bfloat16* __restrict__ hi,
    __nv_bfloat16* __restrict__ lo)
{
    const int i = (blockIdx.x * 256 + threadIdx.x) * 4;
    float4 v = *(const float4*)&src[i];
    __nv_bfloat16 h0 = __float2bfloat16(v.x), h1 = __float2bfloat16(v.y);
    __nv_bfloat16 h2 = __float2bfloat16(v.z), h3 = __float2bfloat16(v.w);
    __nv_bfloat16 l0 = __float2bfloat16(v.x - __bfloat162float(h0));
    __nv_bfloat16 l1 = __float2bfloat16(v.y - __bfloat162float(h1));
    __nv_bfloat16 l2 = __float2bfloat16(v.z - __bfloat162float(h2));
    __nv_bfloat16 l3 = __float2bfloat16(v.w - __bfloat162float(h3));
    __nv_bfloat162 H[2] = {__halves2bfloat162(h0, h1), __halves2bfloat162(h2, h3)};
    __nv_bfloat162 L[2] = {__halves2bfloat162(l0, l1), __halves2bfloat162(l2, l3)};
    *(uint2*)&hi[i] = *(uint2*)H;
    *(uint2*)&lo[i] = *(uint2*)L;
}

// ---------------------------------------------------------------------------
// Transpose + split: W[1024][N] row-major -> T[rowOff+n][k] bf16 hi/lo (K=1024)
// ---------------------------------------------------------------------------
__global__ __launch_bounds__(256) void transpose_split_kernel(
    const float* __restrict__ W, int N,
    __nv_bfloat16* __restrict__ Thi, __nv_bfloat16* __restrict__ Tlo, int rowOff)
{
    __shared__ float tile[32][33];
    const int tx = threadIdx.x, ty = threadIdx.y;
    const int n0 = blockIdx.x * 32, k0 = blockIdx.y * 32;
    #pragma unroll
    for (int j = ty; j < 32; j += 8)
        tile[j][tx] = W[(k0 + j) * N + n0 + tx];
    __syncthreads();
    #pragma unroll
    for (int j = ty; j < 32; j += 8) {
        float v = tile[tx][j];
        __nv_bfloat16 h = __float2bfloat16(v);
        __nv_bfloat16 l = __float2bfloat16(v - __bfloat162float(h));
        Thi[(rowOff + n0 + j) * 1024 + k0 + tx] = h;
        Tlo[(rowOff + n0 + j) * 1024 + k0 + tx] = l;
    }
}

// ---------------------------------------------------------------------------
// HMMA GEMM v3: D[M,N] = A[M,1024] @ B[N,1024]^T, bf16 hi/lo 3-MMA split.
// 128x256 CTA tile, 256 threads, 8 warps (2m x 4n) x (64x64) warp tile.
// cp.async 2-stage pipeline, 24KB/stage = 48KB static smem, XOR-swizzled
// 32B rows (no padding). Split-major MMA order avoids accumulator RAW chains.
// mode 0: qkv epilogue (RoPE -> g_q/g_k/g_v); mode 1: plain fp32 -> outp.
// ---------------------------------------------------------------------------
__global__ __launch_bounds__(256) void mma_gemm_kernel(
    const __nv_bfloat16* __restrict__ Ahi, const __nv_bfloat16* __restrict__ Alo,
    const __nv_bfloat16* __restrict__ Bhi, const __nv_bfloat16* __restrict__ Blo,
    const float* __restrict__ fc, const float* __restrict__ fs,
    float* __restrict__ outp, int mode)
{
    // [stage]: Ah[128*16] Al[128*16] Bh[256*16] Bl[256*16]  (bf16) = 24KB
    __shared__ __align__(16) __nv_bfloat16 sm[2][12288];

    const int tid  = threadIdx.x;
    const int lane = tid & 31, wid = tid >> 5;
    const int wm = wid & 1, wn = wid >> 1;       // 2m x 4n, 64x64 warp tiles
    const int m0 = blockIdx.y * 128, n0 = blockIdx.x * 256;

    // array byte offsets within a stage
    const uint32_t stage0 = smem_u32(&sm[0][0]);
    const uint32_t stage1 = smem_u32(&sm[1][0]);
    // Ah at +0 (4KB), Al at +4096, Bh at +8192 (8KB), Bl at +16384

    // ---- cp.async mapping ----
    // A arrays: 128 rows x 2 halves; thread t -> row t&127, half t>>7 (1 cp each)
    // B arrays: 256 rows; thread t -> row t, both halves (2 cp each)
    const int ra = tid & 127, ca = tid >> 7;
    const uint32_t dA = swz(ra, ca);
    const uint32_t dB0 = swz(tid, 0), dB1 = swz(tid, 1);
    const __nv_bfloat16* gAh = &Ahi[(m0 + ra) * 1024 + ca * 8];
    const __nv_bfloat16* gAl = &Alo[(m0 + ra) * 1024 + ca * 8];
    const __nv_bfloat16* gBh = &Bhi[(n0 + tid) * 1024];
    const __nv_bfloat16* gBl = &Blo[(n0 + tid) * 1024];

    // ---- ldmatrix bases (within-stage byte offsets) ----
    const int arow = wm * 64 + (lane & 15);
    const uint32_t a_off = swz(arow, (lane & 16) ? 1 : 0);
    const int brow = wn * 64 + (lane & 7) + ((lane & 16) ? 8 : 0);
    const uint32_t b_off = swz(brow, (lane & 8) ? 1 : 0);

    float acc[4][8][4];
    #pragma unroll
    for (int i = 0; i < 4; i++)
        #pragma unroll
        for (int j = 0; j < 8; j++)
            #pragma unroll
            for (int q = 0; q < 4; q++) acc[i][j][q] = 0.f;

    #define ISSUE_STAGE(sbase, go) do {                         \
        CPA16((sbase) + dA,           gAh + (go));              \
        CPA16((sbase) + 4096 + dA,    gAl + (go));              \
        CPA16((sbase) + 8192 + dB0,   gBh + (go));              \
        CPA16((sbase) + 8192 + dB1,   gBh + (go) + 8);          \
        CPA16((sbase) + 16384 + dB0,  gBl + (go));              \
        CPA16((sbase) + 16384 + dB1,  gBl + (go) + 8);          \
    } while (0)

    ISSUE_STAGE(stage0, 0);
    CPA_COMMIT();

    for (int kc = 0; kc < 64; ++kc) {
        CPA_WAIT0();
        __syncthreads();     // stage kc visible; all warps done reading kc-1
        if (kc + 1 < 64) {
            const uint32_t sb = (kc & 1) ? stage0 : stage1;
            ISSUE_STAGE(sb, (kc + 1) * 16);
        }
        CPA_COMMIT();

        const uint32_t sb = (kc & 1) ? stage1 : stage0;
        uint32_t Af[2][4][4], Bf[2][8][2];
        #pragma unroll
        for (int h = 0; h < 2; h++) {
            const uint32_t uA = sb + h * 4096 + a_off;
            const uint32_t uB = sb + 8192 + h * 8192 + b_off;
            #pragma unroll
            for (int mt = 0; mt < 4; mt++) ldsm4(Af[h][mt], uA + mt * 512);
            #pragma unroll
            for (int np = 0; np < 4; np++) {
                uint32_t t[4];
                ldsm4(t, uB + np * 512);
                Bf[h][2 * np][0]     = t[0]; Bf[h][2 * np][1]     = t[1];
                Bf[h][2 * np + 1][0] = t[2]; Bf[h][2 * np + 1][1] = t[3];
            }
        }
        // split-major: consecutive MMAs hit different accumulators
        #pragma unroll
        for (int sp = 0; sp < 3; sp++) {
            const int ha = sp >> 1;   // hi*hi, hi*lo, lo*hi
            const int hb = sp & 1;
            #pragma unroll
            for (int mt = 0; mt < 4; mt++)
                #pragma unroll
                for (int nt = 0; nt < 8; nt++)
                    mma_bf16(acc[mt][nt], Af[ha][mt], Bf[hb][nt]);
        }
    }

    // ---- epilogue (per-8-col-group segment routing; bounds are 8-aligned) ----
    const int g = lane >> 2, t2 = (lane & 3) * 2;
    #pragma unroll
    for (int mt = 0; mt < 4; mt++) {
        #pragma unroll
        for (int h2 = 0; h2 < 2; h2++) {
            const int row = m0 + wm * 64 + mt * 16 + g + h2 * 8;
            const int s   = row & (SS - 1);
            #pragma unroll
            for (int nt = 0; nt < 8; nt++) {
                const int n = n0 + wn * 64 + nt * 8 + t2;    // global col
                float v0 = acc[mt][nt][h2 * 2];
                float v1 = acc[mt][nt][h2 * 2 + 1];
                float* dst; int ld, cc; bool rope;
                if (mode == 1)     { dst = outp; ld = 1024; cc = n;        rope = false; }
                else if (n < 1024) { dst = g_q;  ld = 1024; cc = n;        rope = true;  }
                else if (n < 1280) { dst = g_k;  ld = 256;  cc = n - 1024; rope = true;  }
                else               { dst = g_v;  ld = 256;  cc = n - 1280; rope = false; }
                if (rope) {
                    const int j = (n & 63) >> 1;
                    float c  = fc[s * 32 + j];
                    float sn = fs[s * 32 + j];
                    float o0 = v0 * c  - v1 * sn;
                    float o1 = v0 * sn + v1 * c;
                    v0 = o0; v1 = o1;
                }
                *(float2*)&dst[row * ld + cc] = make_float2(v0, v1);
            }
        }
    }
}

// ---------------------------------------------------------------------------
// Sliding-window attention (f32x2 online softmax; emits bf16 hi/lo).
// ---------------------------------------------------------------------------
__global__ __launch_bounds__(128) void attn_kernel()
{
    __shared__ float Ks[80 * 68];
    __shared__ float Vs[80 * 68];
    const int b   = blockIdx.z;
    const int kvh = blockIdx.y;
    const int qbase  = blockIdx.x * 16;
    const int kstart = max(0, qbase - WIN);
    const int nrows  = qbase + 16 - kstart;    // <= 80
    const int tid = threadIdx.x;

    for (int i = tid; i < nrows * 16; i += 128) {
        int row = i >> 4, c = (i & 15) * 4;
        int gidx = ((b * SS + kstart + row) * KVHn + kvh) * 64 + c;
        *(float4*)&Ks[row * 68 + c] = *(const float4*)&g_k[gidx];
        *(float4*)&Vs[row * 68 + c] = *(const float4*)&g_v[gidx];
    }
    __syncthreads();

    const int half = tid & 1, pair = tid >> 1;
    const int rep = pair & 3, qi = pair >> 2;
    const int qg = qbase + qi;
    const int h  = kvh * 4 + rep;
    const unsigned pmask = 3u << ((tid & 31) & ~1);

    ull q2[16];
    {
        const float4* qp = (const float4*)&g_q[((b * SS + qg) * HH + h) * 64 + half * 32];
        #pragma unroll
        for (int t = 0; t < 8; t++) {
            float4 v = qp[t];
            PACK2(q2[2 * t],     v.x, v.y);
            PACK2(q2[2 * t + 1], v.z, v.w);
        }
    }

    ull acc2[16];
    #pragma unroll
    for (int d = 0; d < 16; d++) acc2[d] = 0ULL;
    float m = -1e30f, l = 0.f;

    const int j0 = max(0, qg - WIN) - kstart;
    const int j1 = qg - kstart;
    for (int j = j0; j <= j1; ++j) {
        const float4* kr = (const float4*)&Ks[j * 68 + half * 32];
        ull d2[4] = {0ULL, 0ULL, 0ULL, 0ULL};
        #pragma unroll
        for (int t = 0; t < 8; t++) {
            float4 kv = kr[t];
            ull k2a, k2b;
            PACK2(k2a, kv.x, kv.y);
            PACK2(k2b, kv.z, kv.w);
            FMA2(d2[(2 * t) & 3],     q2[2 * t],     k2a);
            FMA2(d2[(2 * t + 1) & 3], q2[2 * t + 1], k2b);
        }
        ull s01, s23, sall;
        ADD2(s01, d2[0], d2[1]);
        ADD2(s23, d2[2], d2[3]);
        ADD2(sall, s01, s23);
        float plo, phi;
        UNPACK2(plo, phi, sall);
        float partial = plo + phi;
        float sc = (partial + __shfl_xor_sync(pmask, partial, 1)) * 0.125f;

        if (sc > m) {
            float esc = __expf(m - sc);
            ull esc2; DUP2(esc2, esc);
            l *= esc;
            #pragma unroll
            for (int d = 0; d < 16; d++) { ull t2; MUL2(t2, acc2[d], esc2); acc2[d] = t2; }
            m = sc;
        }
        float p = __expf(sc - m);
        l += p;
        ull p2; DUP2(p2, p);
        const float4* vr = (const float4*)&Vs[j * 68 + half * 32];
        #pragma unroll
        for (int t = 0; t < 8; t++) {
            float4 vv = vr[t];
            ull v2a, v2b;
            PACK2(v2a, vv.x, vv.y);
            PACK2(v2b, vv.z, vv.w);
            FMA2(acc2[2 * t],     v2a, p2);
            FMA2(acc2[2 * t + 1], v2b, p2);
        }
    }

    const float inv = 1.f / l;
    const int obase = (b * SS + qg) * 1024 + h * 64 + half * 32;
    #pragma unroll
    for (int t = 0; t < 16; t++) {
        float x0, x1;
        UNPACK2(x0, x1, acc2[t]);
        x0 *= inv; x1 *= inv;
        __nv_bfloat16 h0 = __float2bfloat16(x0), h1 = __float2bfloat16(x1);
        __nv_bfloat16 l0 = __float2bfloat16(x0 - __bfloat162float(h0));
        __nv_bfloat16 l1 = __float2bfloat16(x1 - __bfloat162float(h1));
        __nv_bfloat162 H = __halves2bfloat162(h0, h1);
        __nv_bfloat162 L = __halves2bfloat162(l0, l1);
        *(uint32_t*)&g_ahi[obase + 2 * t] = *(uint32_t*)&H;
        *(uint32_t*)&g_alo[obase + 2 * t] = *(uint32_t*)&L;
    }
}

// ---------------------------------------------------------------------------
extern "C" void kernel_launch(void* const* d_in, const int* in_sizes, int n_in,
                              void* d_out, int out_size)
{
    const float* x  = (const float*)d_in[0];
    const float* fc = (const float*)d_in[1];
    const float* fs = (const float*)d_in[2];
    const float* wq = (const float*)d_in[3];
    const float* wk = (const float*)d_in[4];
    const float* wv = (const float*)d_in[5];
    const float* wo = (const float*)d_in[6];
    float* out = (float*)d_out;

    __nv_bfloat16 *xhi, *xlo, *wthi, *wtlo, *wohi, *wolo, *ahi, *alo;
    cudaGetSymbolAddress((void**)&xhi,  g_xhi);
    cudaGetSymbolAddress((void**)&xlo,  g_xlo);
    cudaGetSymbolAddress((void**)&wthi, g_wt_hi);
    cudaGetSymbolAddress((void**)&wtlo, g_wt_lo);
    cudaGetSymbolAddress((void**)&wohi, g_wo_hi);
    cudaGetSymbolAddress((void**)&wolo, g_wo_lo);
    cudaGetSymbolAddress((void**)&ahi,  g_ahi);
    cudaGetSymbolAddress((void**)&alo,  g_alo);

    // input conversions
    split_kernel<<<MM * DD / 1024, 256>>>(x, xhi, xlo);
    transpose_split_kernel<<<dim3(32, 32), dim3(32, 8)>>>(wq, 1024, wthi, wtlo, 0);
    transpose_split_kernel<<<dim3(8, 32),  dim3(32, 8)>>>(wk, 256,  wthi, wtlo, 1024);
    transpose_split_kernel<<<dim3(8, 32),  dim3(32, 8)>>>(wv, 256,  wthi, wtlo, 1280);
    transpose_split_kernel<<<dim3(32, 32), dim3(32, 8)>>>(wo, 1024, wohi, wolo, 0);

    // QKV projection + RoPE (HMMA, 128x256 tiles)
    mma_gemm_kernel<<<dim3(6, 32), 256>>>(xhi, xlo, wthi, wtlo, fc, fs, nullptr, 0);
    // attention
    attn_kernel<<<dim3(SS / 16, KVHn, BB), 128>>>();
    // output projection (HMMA, 128x256 tiles)
    mma_gemm_kernel<<<dim3(4, 32), 256>>>(ahi, alo, wohi, wolo, nullptr, nullptr, out, 1);
}

// round 10
// speedup vs baseline: 1.2496x; 1.2496x over previous
#include <cuda_runtime.h>
#include <cuda_bf16.h>
#include <cstdint>

#define BB   2
#define SS   2048
#define DD   1024
#define HH   16
#define KVHn 4
#define HD   64
#define WIN  64
#define MM   (BB*SS)   // 4096

typedef unsigned long long ull;

// packed f32x2 helpers (attention kernel)
#define PACK2(d, x, y)  asm("mov.b64 %0, {%1, %2};" : "=l"(d) : "f"(x), "f"(y))
#define DUP2(d, x)      asm("mov.b64 %0, {%1, %1};" : "=l"(d) : "f"(x))
#define UNPACK2(lo, hi, d) asm("mov.b64 {%0, %1}, %2;" : "=f"(lo), "=f"(hi) : "l"(d))
#define FMA2(d, a, b)   asm("fma.rn.f32x2 %0, %1, %2, %0;" : "+l"(d) : "l"(a), "l"(b))
#define MUL2(d, a, b)   asm("mul.rn.f32x2 %0, %1, %2;" : "=l"(d) : "l"(a), "l"(b))
#define ADD2(d, a, b)   asm("add.rn.f32x2 %0, %1, %2;" : "=l"(d) : "l"(a), "l"(b))

__device__ __forceinline__ uint32_t smem_u32(const void* p) {
    uint32_t a;
    asm("{ .reg .u64 t; cvta.to.shared.u64 t, %1; cvt.u32.u64 %0, t; }"
        : "=r"(a) : "l"(p));
    return a;
}

// warp-level tensor core ops (plain sm_80+ ISA, no arch suffix)
__device__ __forceinline__ void ldsm4(uint32_t* r, uint32_t addr) {
    asm volatile("ldmatrix.sync.aligned.m8n8.x4.shared.b16 {%0,%1,%2,%3}, [%4];"
                 : "=r"(r[0]), "=r"(r[1]), "=r"(r[2]), "=r"(r[3]) : "r"(addr));
}
__device__ __forceinline__ void mma_bf16(float* c, const uint32_t* a, const uint32_t* b) {
    asm volatile(
        "mma.sync.aligned.m16n8k16.row.col.f32.bf16.bf16.f32 "
        "{%0,%1,%2,%3}, {%4,%5,%6,%7}, {%8,%9}, {%0,%1,%2,%3};"
        : "+f"(c[0]), "+f"(c[1]), "+f"(c[2]), "+f"(c[3])
        : "r"(a[0]), "r"(a[1]), "r"(a[2]), "r"(a[3]), "r"(b[0]), "r"(b[1]));
}

// ---------------------------------------------------------------------------
// Device scratch
// ---------------------------------------------------------------------------
__device__ float g_q[MM * HH * HD];
__device__ float g_k[MM * KVHn * HD];
__device__ float g_v[MM * KVHn * HD];
__device__ __nv_bfloat16 g_xhi[MM * DD],  g_xlo[MM * DD];          // x split
__device__ __nv_bfloat16 g_wt_hi[1536 * DD], g_wt_lo[1536 * DD];   // [wq|wk|wv]^T
__device__ __nv_bfloat16 g_wo_hi[DD * DD],   g_wo_lo[DD * DD];     // wo^T
__device__ __nv_bfloat16 g_ahi[MM * DD],  g_alo[MM * DD];          // attn out split

// ---------------------------------------------------------------------------
// Split fp32 -> bf16 hi/lo (no transpose). 4 elems/thread.
// ---------------------------------------------------------------------------
__global__ __launch_bounds__(256) void split_kernel(
    const float* __restrict__ src, __nv_bfloat16* __restrict__ hi,
    __nv_bfloat16* __restrict__ lo)
{
    const int i = (blockIdx.x * 256 + threadIdx.x) * 4;
    float4 v = *(const float4*)&src[i];
    __nv_bfloat16 h0 = __float2bfloat16(v.x), h1 = __float2bfloat16(v.y);
    __nv_bfloat16 h2 = __float2bfloat16(v.z), h3 = __float2bfloat16(v.w);
    __nv_bfloat16 l0 = __float2bfloat16(v.x - __bfloat162float(h0));
    __nv_bfloat16 l1 = __float2bfloat16(v.y - __bfloat162float(h1));
    __nv_bfloat16 l2 = __float2bfloat16(v.z - __bfloat162float(h2));
    __nv_bfloat16 l3 = __float2bfloat16(v.w - __bfloat162float(h3));
    __nv_bfloat162 H[2] = {__halves2bfloat162(h0, h1), __halves2bfloat162(h2, h3)};
    __nv_bfloat162 L[2] = {__halves2bfloat162(l0, l1), __halves2bfloat162(l2, l3)};
    *(uint2*)&hi[i] = *(uint2*)H;
    *(uint2*)&lo[i] = *(uint2*)L;
}

// ---------------------------------------------------------------------------
// Transpose + split: W[1024][N] row-major -> T[rowOff+n][k] bf16 hi/lo (K=1024)
// ---------------------------------------------------------------------------
__global__ __launch_bounds__(256) void transpose_split_kernel(
    const float* __restrict__ W, int N,
    __nv_bfloat16* __restrict__ Thi, __nv_bfloat16* __restrict__ Tlo, int rowOff)
{
    __shared__ float tile[32][33];
    const int tx = threadIdx.x, ty = threadIdx.y;
    const int n0 = blockIdx.x * 32, k0 = blockIdx.y * 32;
    #pragma unroll
    for (int j = ty; j < 32; j += 8)
        tile[j][tx] = W[(k0 + j) * N + n0 + tx];
    __syncthreads();
    #pragma unroll
    for (int j = ty; j < 32; j += 8) {
        float v = tile[tx][j];
        __nv_bfloat16 h = __float2bfloat16(v);
        __nv_bfloat16 l = __float2bfloat16(v - __bfloat162float(h));
        Thi[(rowOff + n0 + j) * 1024 + k0 + tx] = h;
        Tlo[(rowOff + n0 + j) * 1024 + k0 + tx] = l;
    }
}

// ---------------------------------------------------------------------------
// HMMA GEMM (R6 structure + split-major MMA order): D = A[M,1024] @ B[N,1024]^T,
// bf16 hi/lo 3-MMA split, fp32 accumulators. 128x128x32 CTA tile, 8 warps x
// (64x32) warp tile. 80B-padded smem rows (conflict-free ldmatrix). Register
// prefetch overlaps gmem with MMA. Split-major ordering: all hi*hi MMAs, then
// hi*lo, then lo*hi -> consecutive HMMAs hit different accumulators (no RAW).
// mode 0: qkv epilogue (RoPE -> g_q/g_k/g_v); mode 1: plain fp32 -> outp.
// ---------------------------------------------------------------------------
__global__ __launch_bounds__(256) void mma_gemm_kernel(
    const __nv_bfloat16* __restrict__ Ahi, const __nv_bfloat16* __restrict__ Alo,
    const __nv_bfloat16* __restrict__ Bhi, const __nv_bfloat16* __restrict__ Blo,
    const float* __restrict__ fc, const float* __restrict__ fs,
    float* __restrict__ outp, int mode)
{
    // 4 tiles x 128 rows x 40 bf16 (32 data + 8 pad) = 40960 B static smem
    __shared__ __align__(16) __nv_bfloat16 sAh[128 * 40], sAl[128 * 40];
    __shared__ __align__(16) __nv_bfloat16 sBh[128 * 40], sBl[128 * 40];

    const int tid  = threadIdx.x;
    const int lane = tid & 31, wid = tid >> 5;
    const int wm = wid & 1, wn = wid >> 1;       // warp grid 2m x 4n
    const int m0 = blockIdx.y * 128, n0 = blockIdx.x * 128;

    // ---- gmem load mapping: thread covers one row, 32B (2 int4) ----
    const int lr = tid >> 1, lc = (tid & 1) * 16;          // row 0..127, col 0/16
    const __nv_bfloat16* pAh = &Ahi[(m0 + lr) * 1024 + lc];
    const __nv_bfloat16* pAl = &Alo[(m0 + lr) * 1024 + lc];
    const __nv_bfloat16* pBh = &Bhi[(n0 + lr) * 1024 + lc];
    const __nv_bfloat16* pBl = &Blo[(n0 + lr) * 1024 + lc];
    const int ss = lr * 40 + lc;                            // smem elem offset

    // ---- ldmatrix address bases (byte offsets into each tile) ----
    const uint32_t a_base = ((wm * 64 + (lane & 15)) * 40 + ((lane & 16) ? 8 : 0)) * 2;
    const uint32_t b_base = ((wn * 32 + (lane & 7) + ((lane & 16) ? 8 : 0)) * 40
                             + ((lane & 8) ? 8 : 0)) * 2;
    const uint32_t uAh = smem_u32(sAh) + a_base, uAl = smem_u32(sAl) + a_base;
    const uint32_t uBh = smem_u32(sBh) + b_base, uBl = smem_u32(sBl) + b_base;

    float acc[4][4][4];
    #pragma unroll
    for (int i = 0; i < 4; i++)
        #pragma unroll
        for (int j = 0; j < 4; j++)
            #pragma unroll
            for (int q = 0; q < 4; q++) acc[i][j][q] = 0.f;

    int4 pr[8];
    #define PREF(koff) do {                                   \
        pr[0] = *(const int4*)&pAh[koff];                     \
        pr[1] = *(const int4*)&pAh[(koff) + 8];               \
        pr[2] = *(const int4*)&pAl[koff];                     \
        pr[3] = *(const int4*)&pAl[(koff) + 8];               \
        pr[4] = *(const int4*)&pBh[koff];                     \
        pr[5] = *(const int4*)&pBh[(koff) + 8];               \
        pr[6] = *(const int4*)&pBl[koff];                     \
        pr[7] = *(const int4*)&pBl[(koff) + 8];               \
    } while (0)

    PREF(0);
    for (int kc = 0; kc < 32; ++kc) {
        if (kc) __syncthreads();                  // prior reads done
        *(int4*)&sAh[ss]     = pr[0];
        *(int4*)&sAh[ss + 8] = pr[1];
        *(int4*)&sAl[ss]     = pr[2];
        *(int4*)&sAl[ss + 8] = pr[3];
        *(int4*)&sBh[ss]     = pr[4];
        *(int4*)&sBh[ss + 8] = pr[5];
        *(int4*)&sBl[ss]     = pr[6];
        *(int4*)&sBl[ss + 8] = pr[7];
        __syncthreads();
        if (kc < 31) PREF((kc + 1) * 32);         // in flight during MMA

        #pragma unroll
        for (int ks = 0; ks < 2; ++ks) {          // two k16 steps per chunk
            const uint32_t kb = ks * 32;          // 16 bf16 = 32 bytes
            uint32_t Af[2][4][4];                 // [hi/lo][mt][reg]
            uint32_t Bf[2][4][2];                 // [hi/lo][nt][reg]
            #pragma unroll
            for (int mt = 0; mt < 4; mt++) {
                ldsm4(Af[0][mt], uAh + mt * 16 * 80 + kb);
                ldsm4(Af[1][mt], uAl + mt * 16 * 80 + kb);
            }
            #pragma unroll
            for (int np = 0; np < 2; np++) {
                uint32_t t[4];
                ldsm4(t, uBh + np * 16 * 80 + kb);
                Bf[0][2*np][0] = t[0]; Bf[0][2*np][1] = t[1];
                Bf[0][2*np+1][0] = t[2]; Bf[0][2*np+1][1] = t[3];
                ldsm4(t, uBl + np * 16 * 80 + kb);
                Bf[1][2*np][0] = t[0]; Bf[1][2*np][1] = t[1];
                Bf[1][2*np+1][0] = t[2]; Bf[1][2*np+1][1] = t[3];
            }
            // split-major: consecutive MMAs hit different accumulators
            #pragma unroll
            for (int sp = 0; sp < 3; sp++) {
                const int ha = sp >> 1;   // 0,0,1 : hi*hi, hi*lo, lo*hi
                const int hb = sp & 1;
                #pragma unroll
                for (int mt = 0; mt < 4; mt++)
                    #pragma unroll
                    for (int nt = 0; nt < 4; nt++)
                        mma_bf16(acc[mt][nt], Af[ha][mt], Bf[hb][nt]);
            }
        }
    }

    // ---- epilogue ----
    const int g = lane >> 2, t2 = (lane & 3) * 2;
    float* dst; int ld, coff; bool rope;
    if (mode == 1)      { dst = outp; ld = 1024; coff = n0;        rope = false; }
    else if (n0 < 1024) { dst = g_q;  ld = 1024; coff = n0;        rope = true;  }
    else if (n0 < 1280) { dst = g_k;  ld = 256;  coff = n0 - 1024; rope = true;  }
    else                { dst = g_v;  ld = 256;  coff = n0 - 1280; rope = false; }

    #pragma unroll
    for (int mt = 0; mt < 4; mt++) {
        #pragma unroll
        for (int h2 = 0; h2 < 2; h2++) {
            const int row = m0 + wm * 64 + mt * 16 + g + h2 * 8;
            const int s   = row & (SS - 1);
            #pragma unroll
            for (int nt = 0; nt < 4; nt++) {
                const int col = wn * 32 + nt * 8 + t2;   // 0..127 in block
                float v0 = acc[mt][nt][h2 * 2];
                float v1 = acc[mt][nt][h2 * 2 + 1];
                if (rope) {
                    const int j = ((n0 + col) & 63) >> 1;
                    float c  = fc[s * 32 + j];
                    float sn = fs[s * 32 + j];
                    float o0 = v0 * c  - v1 * sn;
                    float o1 = v0 * sn + v1 * c;
                    v0 = o0; v1 = o1;
                }
                *(float2*)&dst[row * ld + coff + col] = make_float2(v0, v1);
            }
        }
    }
}

// ---------------------------------------------------------------------------
// Sliding-window attention (f32x2 online softmax; emits bf16 hi/lo).
// ---------------------------------------------------------------------------
__global__ __launch_bounds__(128) void attn_kernel()
{
    __shared__ float Ks[80 * 68];
    __shared__ float Vs[80 * 68];
    const int b   = blockIdx.z;
    const int kvh = blockIdx.y;
    const int qbase  = blockIdx.x * 16;
    const int kstart = max(0, qbase - WIN);
    const int nrows  = qbase + 16 - kstart;    // <= 80
    const int tid = threadIdx.x;

    for (int i = tid; i < nrows * 16; i += 128) {
        int row = i >> 4, c = (i & 15) * 4;
        int gidx = ((b * SS + kstart + row) * KVHn + kvh) * 64 + c;
        *(float4*)&Ks[row * 68 + c] = *(const float4*)&g_k[gidx];
        *(float4*)&Vs[row * 68 + c] = *(const float4*)&g_v[gidx];
    }
    __syncthreads();

    const int half = tid & 1, pair = tid >> 1;
    const int rep = pair & 3, qi = pair >> 2;
    const int qg = qbase + qi;
    const int h  = kvh * 4 + rep;
    const unsigned pmask = 3u << ((tid & 31) & ~1);

    ull q2[16];
    {
        const float4* qp = (const float4*)&g_q[((b * SS + qg) * HH + h) * 64 + half * 32];
        #pragma unroll
        for (int t = 0; t < 8; t++) {
            float4 v = qp[t];
            PACK2(q2[2 * t],     v.x, v.y);
            PACK2(q2[2 * t + 1], v.z, v.w);
        }
    }

    ull acc2[16];
    #pragma unroll
    for (int d = 0; d < 16; d++) acc2[d] = 0ULL;
    float m = -1e30f, l = 0.f;

    const int j0 = max(0, qg - WIN) - kstart;
    const int j1 = qg - kstart;
    for (int j = j0; j <= j1; ++j) {
        const float4* kr = (const float4*)&Ks[j * 68 + half * 32];
        ull d2[4] = {0ULL, 0ULL, 0ULL, 0ULL};
        #pragma unroll
        for (int t = 0; t < 8; t++) {
            float4 kv = kr[t];
            ull k2a, k2b;
            PACK2(k2a, kv.x, kv.y);
            PACK2(k2b, kv.z, kv.w);
            FMA2(d2[(2 * t) & 3],     q2[2 * t],     k2a);
            FMA2(d2[(2 * t + 1) & 3], q2[2 * t + 1], k2b);
        }
        ull s01, s23, sall;
        ADD2(s01, d2[0], d2[1]);
        ADD2(s23, d2[2], d2[3]);
        ADD2(sall, s01, s23);
        float plo, phi;
        UNPACK2(plo, phi, sall);
        float partial = plo + phi;
        float sc = (partial + __shfl_xor_sync(pmask, partial, 1)) * 0.125f;

        if (sc > m) {
            float esc = __expf(m - sc);
            ull esc2; DUP2(esc2, esc);
            l *= esc;
            #pragma unroll
            for (int d = 0; d < 16; d++) { ull t2; MUL2(t2, acc2[d], esc2); acc2[d] = t2; }
            m = sc;
        }
        float p = __expf(sc - m);
        l += p;
        ull p2; DUP2(p2, p);
        const float4* vr = (const float4*)&Vs[j * 68 + half * 32];
        #pragma unroll
        for (int t = 0; t < 8; t++) {
            float4 vv = vr[t];
            ull v2a, v2b;
            PACK2(v2a, vv.x, vv.y);
            PACK2(v2b, vv.z, vv.w);
            FMA2(acc2[2 * t],     v2a, p2);
            FMA2(acc2[2 * t + 1], v2b, p2);
        }
    }

    const float inv = 1.f / l;
    const int obase = (b * SS + qg) * 1024 + h * 64 + half * 32;
    #pragma unroll
    for (int t = 0; t < 16; t++) {
        float x0, x1;
        UNPACK2(x0, x1, acc2[t]);
        x0 *= inv; x1 *= inv;
        __nv_bfloat16 h0 = __float2bfloat16(x0), h1 = __float2bfloat16(x1);
        __nv_bfloat16 l0 = __float2bfloat16(x0 - __bfloat162float(h0));
        __nv_bfloat16 l1 = __float2bfloat16(x1 - __bfloat162float(h1));
        __nv_bfloat162 H = __halves2bfloat162(h0, h1);
        __nv_bfloat162 L = __halves2bfloat162(l0, l1);
        *(uint32_t*)&g_ahi[obase + 2 * t] = *(uint32_t*)&H;
        *(uint32_t*)&g_alo[obase + 2 * t] = *(uint32_t*)&L;
    }
}

// ---------------------------------------------------------------------------
extern "C" void kernel_launch(void* const* d_in, const int* in_sizes, int n_in,
                              void* d_out, int out_size)
{
    const float* x  = (const float*)d_in[0];
    const float* fc = (const float*)d_in[1];
    const float* fs = (const float*)d_in[2];
    const float* wq = (const float*)d_in[3];
    const float* wk = (const float*)d_in[4];
    const float* wv = (const float*)d_in[5];
    const float* wo = (const float*)d_in[6];
    float* out = (float*)d_out;

    __nv_bfloat16 *xhi, *xlo, *wthi, *wtlo, *wohi, *wolo, *ahi, *alo;
    cudaGetSymbolAddress((void**)&xhi,  g_xhi);
    cudaGetSymbolAddress((void**)&xlo,  g_xlo);
    cudaGetSymbolAddress((void**)&wthi, g_wt_hi);
    cudaGetSymbolAddress((void**)&wtlo, g_wt_lo);
    cudaGetSymbolAddress((void**)&wohi, g_wo_hi);
    cudaGetSymbolAddress((void**)&wolo, g_wo_lo);
    cudaGetSymbolAddress((void**)&ahi,  g_ahi);
    cudaGetSymbolAddress((void**)&alo,  g_alo);

    // input conversions
    split_kernel<<<MM * DD / 1024, 256>>>(x, xhi, xlo);
    transpose_split_kernel<<<dim3(32, 32), dim3(32, 8)>>>(wq, 1024, wthi, wtlo, 0);
    transpose_split_kernel<<<dim3(8, 32),  dim3(32, 8)>>>(wk, 256,  wthi, wtlo, 1024);
    transpose_split_kernel<<<dim3(8, 32),  dim3(32, 8)>>>(wv, 256,  wthi, wtlo, 1280);
    transpose_split_kernel<<<dim3(32, 32), dim3(32, 8)>>>(wo, 1024, wohi, wolo, 0);

    // QKV projection + RoPE (HMMA)
    mma_gemm_kernel<<<dim3(12, 32), 256>>>(xhi, xlo, wthi, wtlo, fc, fs, nullptr, 0);
    // attention
    attn_kernel<<<dim3(SS / 16, KVHn, BB), 128>>>();
    // output projection (HMMA)
    mma_gemm_kernel<<<dim3(8, 32), 256>>>(ahi, alo, wohi, wolo, nullptr, nullptr, out, 1);
}

// round 11
// speedup vs baseline: 1.4319x; 1.1459x over previous
#include <cuda_runtime.h>
#include <cuda_bf16.h>
#include <cstdint>

#define BB   2
#define SS   2048
#define DD   1024
#define HH   16
#define KVHn 4
#define HD   64
#define WIN  64
#define MM   (BB*SS)   // 4096

typedef unsigned long long ull;

// packed f32x2 helpers (attention kernel)
#define PACK2(d, x, y)  asm("mov.b64 %0, {%1, %2};" : "=l"(d) : "f"(x), "f"(y))
#define DUP2(d, x)      asm("mov.b64 %0, {%1, %1};" : "=l"(d) : "f"(x))
#define UNPACK2(lo, hi, d) asm("mov.b64 {%0, %1}, %2;" : "=f"(lo), "=f"(hi) : "l"(d))
#define FMA2(d, a, b)   asm("fma.rn.f32x2 %0, %1, %2, %0;" : "+l"(d) : "l"(a), "l"(b))
#define MUL2(d, a, b)   asm("mul.rn.f32x2 %0, %1, %2;" : "=l"(d) : "l"(a), "l"(b))
#define ADD2(d, a, b)   asm("add.rn.f32x2 %0, %1, %2;" : "=l"(d) : "l"(a), "l"(b))

__device__ __forceinline__ uint32_t smem_u32(const void* p) {
    uint32_t a;
    asm("{ .reg .u64 t; cvta.to.shared.u64 t, %1; cvt.u32.u64 %0, t; }"
        : "=r"(a) : "l"(p));
    return a;
}

// warp-level tensor core ops (plain sm_80+ ISA, no arch suffix)
__device__ __forceinline__ void ldsm4(uint32_t* r, uint32_t addr) {
    asm volatile("ldmatrix.sync.aligned.m8n8.x4.shared.b16 {%0,%1,%2,%3}, [%4];"
                 : "=r"(r[0]), "=r"(r[1]), "=r"(r[2]), "=r"(r[3]) : "r"(addr));
}
__device__ __forceinline__ void mma_tf32(float* c, const uint32_t* a, const uint32_t* b) {
    asm volatile(
        "mma.sync.aligned.m16n8k8.row.col.f32.tf32.tf32.f32 "
        "{%0,%1,%2,%3}, {%4,%5,%6,%7}, {%8,%9}, {%0,%1,%2,%3};"
        : "+f"(c[0]), "+f"(c[1]), "+f"(c[2]), "+f"(c[3])
        : "r"(a[0]), "r"(a[1]), "r"(a[2]), "r"(a[3]), "r"(b[0]), "r"(b[1]));
}
__device__ __forceinline__ uint32_t f2tf(uint32_t fbits) {
    uint32_t r;
    asm("cvt.rna.tf32.f32 %0, %1;" : "=r"(r) : "f"(__uint_as_float(fbits)));
    return r;
}
__device__ __forceinline__ int4 cvt4(int4 v) {
    int4 o;
    o.x = (int)f2tf((uint32_t)v.x);
    o.y = (int)f2tf((uint32_t)v.y);
    o.z = (int)f2tf((uint32_t)v.z);
    o.w = (int)f2tf((uint32_t)v.w);
    return o;
}

// ---------------------------------------------------------------------------
// Device scratch
// ---------------------------------------------------------------------------
__device__ float g_q[MM * HH * HD];
__device__ float g_k[MM * KVHn * HD];
__device__ float g_v[MM * KVHn * HD];
__device__ float g_att[MM * HH * HD];       // attention output (fp32)
__device__ float g_wt[1536 * DD];           // [wq|wk|wv]^T  (fp32, [N,K])
__device__ float g_wo_t[DD * DD];           // wo^T          (fp32, [N,K])

// ---------------------------------------------------------------------------
// Transpose: W[1024][N] row-major -> T[rowOff+n][k], fp32. 32x32 tile + pad.
// ---------------------------------------------------------------------------
__global__ __launch_bounds__(256) void transpose_kernel(
    const float* __restrict__ W, int N, float* __restrict__ T, int rowOff)
{
    __shared__ float tile[32][33];
    const int tx = threadIdx.x, ty = threadIdx.y;
    const int n0 = blockIdx.x * 32, k0 = blockIdx.y * 32;
    #pragma unroll
    for (int j = ty; j < 32; j += 8)
        tile[j][tx] = W[(k0 + j) * N + n0 + tx];
    __syncthreads();
    #pragma unroll
    for (int j = ty; j < 32; j += 8)
        T[(rowOff + n0 + j) * 1024 + k0 + tx] = tile[tx][j];
}

// ---------------------------------------------------------------------------
// tf32 HMMA GEMM: D[M,N] = A[M,1024] @ B[N,1024]^T, fp32 in (tf32-rounded
// in-kernel), fp32 accumulate. 128x128x32 CTA tile, 8 warps x (64x32) warp
// tile, m16n8k8 MMA. Smem rows 144B (128B data + 16B pad -> conflict-free
// ldmatrix). Register prefetch overlaps gmem with MMA (R6-proven schedule).
// mode 0: qkv epilogue (RoPE -> g_q/g_k/g_v); mode 1: plain fp32 -> outp.
// ---------------------------------------------------------------------------
__global__ __launch_bounds__(256) void mma_gemm_kernel(
    const float* __restrict__ A, const float* __restrict__ B,
    const float* __restrict__ fc, const float* __restrict__ fs,
    float* __restrict__ outp, int mode)
{
    // 2 arrays x 128 rows x 36 floats (32 data + 4 pad) = 36864 B static smem
    __shared__ __align__(16) float sA[128 * 36];
    __shared__ __align__(16) float sB[128 * 36];

    const int tid  = threadIdx.x;
    const int lane = tid & 31, wid = tid >> 5;
    const int wm = wid & 1, wn = wid >> 1;       // warp grid 2m x 4n
    const int m0 = blockIdx.y * 128, n0 = blockIdx.x * 128;

    // ---- gmem load mapping: thread covers one row, 64B (4 int4) ----
    const int lr = tid >> 1, lcw = (tid & 1) * 16;   // row 0..127, float col 0/16
    const float* pA = &A[(m0 + lr) * 1024 + lcw];
    const float* pB = &B[(n0 + lr) * 1024 + lcw];
    const int ss = lr * 36 + lcw;                    // smem float offset

    // ---- ldmatrix address bases (byte offsets) ----
    // A matrices: [r0-7,k0-3],[r8-15,k0-3],[r0-7,k4-7],[r8-15,k4-7]
    const int arow = wm * 64 + (lane & 7) + ((lane & 8) ? 8 : 0);
    const uint32_t a_base = arow * 144 + ((lane & 16) ? 16 : 0);
    // B matrices: [n0-7,k0-3],[n0-7,k4-7],[n8-15,k0-3],[n8-15,k4-7]
    const int brow = wn * 32 + (lane & 7) + ((lane & 16) ? 8 : 0);
    const uint32_t b_base = brow * 144 + ((lane & 8) ? 16 : 0);
    const uint32_t uA = smem_u32(sA) + a_base;
    const uint32_t uB = smem_u32(sB) + b_base;

    float acc[4][4][4];
    #pragma unroll
    for (int i = 0; i < 4; i++)
        #pragma unroll
        for (int j = 0; j < 4; j++)
            #pragma unroll
            for (int q = 0; q < 4; q++) acc[i][j][q] = 0.f;

    int4 pr[8];
    #define PREF(koff) do {                                   \
        pr[0] = *(const int4*)&pA[koff];                      \
        pr[1] = *(const int4*)&pA[(koff) + 4];                \
        pr[2] = *(const int4*)&pA[(koff) + 8];                \
        pr[3] = *(const int4*)&pA[(koff) + 12];               \
        pr[4] = *(const int4*)&pB[koff];                      \
        pr[5] = *(const int4*)&pB[(koff) + 4];                \
        pr[6] = *(const int4*)&pB[(koff) + 8];                \
        pr[7] = *(const int4*)&pB[(koff) + 12];               \
    } while (0)

    PREF(0);
    for (int kc = 0; kc < 32; ++kc) {
        if (kc) __syncthreads();                  // prior reads done
        *(int4*)&sA[ss]      = cvt4(pr[0]);       // tf32-round on the way in
        *(int4*)&sA[ss + 4]  = cvt4(pr[1]);
        *(int4*)&sA[ss + 8]  = cvt4(pr[2]);
        *(int4*)&sA[ss + 12] = cvt4(pr[3]);
        *(int4*)&sB[ss]      = cvt4(pr[4]);
        *(int4*)&sB[ss + 4]  = cvt4(pr[5]);
        *(int4*)&sB[ss + 8]  = cvt4(pr[6]);
        *(int4*)&sB[ss + 12] = cvt4(pr[7]);
        __syncthreads();
        if (kc < 31) PREF((kc + 1) * 32);         // in flight during MMA

        #pragma unroll
        for (int ks = 0; ks < 4; ++ks) {          // four k8 steps per chunk
            const uint32_t kb = ks * 32;          // 8 tf32 = 32 bytes
            uint32_t Af[4][4], Bf[4][2];
            #pragma unroll
            for (int mt = 0; mt < 4; mt++)
                ldsm4(Af[mt], uA + mt * 16 * 144 + kb);
            #pragma unroll
            for (int np = 0; np < 2; np++) {
                uint32_t t[4];
                ldsm4(t, uB + np * 16 * 144 + kb);
                Bf[2*np][0]   = t[0]; Bf[2*np][1]   = t[1];
                Bf[2*np+1][0] = t[2]; Bf[2*np+1][1] = t[3];
            }
            #pragma unroll
            for (int mt = 0; mt < 4; mt++)
                #pragma unroll
                for (int nt = 0; nt < 4; nt++)
                    mma_tf32(acc[mt][nt], Af[mt], Bf[nt]);
        }
    }

    // ---- epilogue ----
    const int g = lane >> 2, t2 = (lane & 3) * 2;
    float* dst; int ld, coff; bool rope;
    if (mode == 1)      { dst = outp;  ld = 1024; coff = n0;        rope = false; }
    else if (n0 < 1024) { dst = g_q;   ld = 1024; coff = n0;        rope = true;  }
    else if (n0 < 1280) { dst = g_k;   ld = 256;  coff = n0 - 1024; rope = true;  }
    else                { dst = g_v;   ld = 256;  coff = n0 - 1280; rope = false; }

    #pragma unroll
    for (int mt = 0; mt < 4; mt++) {
        #pragma unroll
        for (int h2 = 0; h2 < 2; h2++) {
            const int row = m0 + wm * 64 + mt * 16 + g + h2 * 8;
            const int s   = row & (SS - 1);
            #pragma unroll
            for (int nt = 0; nt < 4; nt++) {
                const int col = wn * 32 + nt * 8 + t2;   // 0..127 in block
                float v0 = acc[mt][nt][h2 * 2];
                float v1 = acc[mt][nt][h2 * 2 + 1];
                if (rope) {
                    const int j = ((n0 + col) & 63) >> 1;
                    float c  = fc[s * 32 + j];
                    float sn = fs[s * 32 + j];
                    float o0 = v0 * c  - v1 * sn;
                    float o1 = v0 * sn + v1 * c;
                    v0 = o0; v1 = o1;
                }
                *(float2*)&dst[row * ld + coff + col] = make_float2(v0, v1);
            }
        }
    }
}

// ---------------------------------------------------------------------------
// Sliding-window attention (f32x2 online softmax; emits fp32 g_att).
// ---------------------------------------------------------------------------
__global__ __launch_bounds__(128) void attn_kernel()
{
    __shared__ float Ks[80 * 68];
    __shared__ float Vs[80 * 68];
    const int b   = blockIdx.z;
    const int kvh = blockIdx.y;
    const int qbase  = blockIdx.x * 16;
    const int kstart = max(0, qbase - WIN);
    const int nrows  = qbase + 16 - kstart;    // <= 80
    const int tid = threadIdx.x;

    for (int i = tid; i < nrows * 16; i += 128) {
        int row = i >> 4, c = (i & 15) * 4;
        int gidx = ((b * SS + kstart + row) * KVHn + kvh) * 64 + c;
        *(float4*)&Ks[row * 68 + c] = *(const float4*)&g_k[gidx];
        *(float4*)&Vs[row * 68 + c] = *(const float4*)&g_v[gidx];
    }
    __syncthreads();

    const int half = tid & 1, pair = tid >> 1;
    const int rep = pair & 3, qi = pair >> 2;
    const int qg = qbase + qi;
    const int h  = kvh * 4 + rep;
    const unsigned pmask = 3u << ((tid & 31) & ~1);

    ull q2[16];
    {
        const float4* qp = (const float4*)&g_q[((b * SS + qg) * HH + h) * 64 + half * 32];
        #pragma unroll
        for (int t = 0; t < 8; t++) {
            float4 v = qp[t];
            PACK2(q2[2 * t],     v.x, v.y);
            PACK2(q2[2 * t + 1], v.z, v.w);
        }
    }

    ull acc2[16];
    #pragma unroll
    for (int d = 0; d < 16; d++) acc2[d] = 0ULL;
    float m = -1e30f, l = 0.f;

    const int j0 = max(0, qg - WIN) - kstart;
    const int j1 = qg - kstart;
    for (int j = j0; j <= j1; ++j) {
        const float4* kr = (const float4*)&Ks[j * 68 + half * 32];
        ull d2[4] = {0ULL, 0ULL, 0ULL, 0ULL};
        #pragma unroll
        for (int t = 0; t < 8; t++) {
            float4 kv = kr[t];
            ull k2a, k2b;
            PACK2(k2a, kv.x, kv.y);
            PACK2(k2b, kv.z, kv.w);
            FMA2(d2[(2 * t) & 3],     q2[2 * t],     k2a);
            FMA2(d2[(2 * t + 1) & 3], q2[2 * t + 1], k2b);
        }
        ull s01, s23, sall;
        ADD2(s01, d2[0], d2[1]);
        ADD2(s23, d2[2], d2[3]);
        ADD2(sall, s01, s23);
        float plo, phi;
        UNPACK2(plo, phi, sall);
        float partial = plo + phi;
        float sc = (partial + __shfl_xor_sync(pmask, partial, 1)) * 0.125f;

        if (sc > m) {
            float esc = __expf(m - sc);
            ull esc2; DUP2(esc2, esc);
            l *= esc;
            #pragma unroll
            for (int d = 0; d < 16; d++) { ull t2; MUL2(t2, acc2[d], esc2); acc2[d] = t2; }
            m = sc;
        }
        float p = __expf(sc - m);
        l += p;
        ull p2; DUP2(p2, p);
        const float4* vr = (const float4*)&Vs[j * 68 + half * 32];
        #pragma unroll
        for (int t = 0; t < 8; t++) {
            float4 vv = vr[t];
            ull v2a, v2b;
            PACK2(v2a, vv.x, vv.y);
            PACK2(v2b, vv.z, vv.w);
            FMA2(acc2[2 * t],     v2a, p2);
            FMA2(acc2[2 * t + 1], v2b, p2);
        }
    }

    const float inv = 1.f / l;
    float* op = &g_att[(b * SS + qg) * 1024 + h * 64 + half * 32];
    #pragma unroll
    for (int t = 0; t < 8; t++) {
        float x0, x1, x2, x3;
        UNPACK2(x0, x1, acc2[2 * t]);
        UNPACK2(x2, x3, acc2[2 * t + 1]);
        *(float4*)&op[t * 4] = make_float4(x0 * inv, x1 * inv, x2 * inv, x3 * inv);
    }
}

// ---------------------------------------------------------------------------
extern "C" void kernel_launch(void* const* d_in, const int* in_sizes, int n_in,
                              void* d_out, int out_size)
{
    const float* x  = (const float*)d_in[0];
    const float* fc = (const float*)d_in[1];
    const float* fs = (const float*)d_in[2];
    const float* wq = (const float*)d_in[3];
    const float* wk = (const float*)d_in[4];
    const float* wv = (const float*)d_in[5];
    const float* wo = (const float*)d_in[6];
    float* out = (float*)d_out;

    float *wt, *wot, *att;
    cudaGetSymbolAddress((void**)&wt,  g_wt);
    cudaGetSymbolAddress((void**)&wot, g_wo_t);
    cudaGetSymbolAddress((void**)&att, g_att);

    // weight transposes (fp32; tf32 rounding happens inside the GEMM)
    transpose_kernel<<<dim3(32, 32), dim3(32, 8)>>>(wq, 1024, wt, 0);
    transpose_kernel<<<dim3(8, 32),  dim3(32, 8)>>>(wk, 256,  wt, 1024);
    transpose_kernel<<<dim3(8, 32),  dim3(32, 8)>>>(wv, 256,  wt, 1280);
    transpose_kernel<<<dim3(32, 32), dim3(32, 8)>>>(wo, 1024, wot, 0);

    // QKV projection + RoPE (tf32 HMMA; x consumed directly as fp32)
    mma_gemm_kernel<<<dim3(12, 32), 256>>>(x, wt, fc, fs, nullptr, 0);
    // attention
    attn_kernel<<<dim3(SS / 16, KVHn, BB), 128>>>();
    // output projection (tf32 HMMA)
    mma_gemm_kernel<<<dim3(8, 32), 256>>>(att, wot, nullptr, nullptr, out, 1);
}

// round 12
// speedup vs baseline: 1.7818x; 1.2443x over previous
#include <cuda_runtime.h>
#include <cuda_bf16.h>
#include <cstdint>

#define BB   2
#define SS   2048
#define DD   1024
#define HH   16
#define KVHn 4
#define HD   64
#define WIN  64
#define MM   (BB*SS)   // 4096

typedef unsigned long long ull;

__device__ __forceinline__ uint32_t smem_u32(const void* p) {
    uint32_t a;
    asm("{ .reg .u64 t; cvta.to.shared.u64 t, %1; cvt.u32.u64 %0, t; }"
        : "=r"(a) : "l"(p));
    return a;
}

// warp-level tensor core ops (plain sm_80+ ISA, no arch suffix)
__device__ __forceinline__ void ldsm4(uint32_t* r, uint32_t addr) {
    asm volatile("ldmatrix.sync.aligned.m8n8.x4.shared.b16 {%0,%1,%2,%3}, [%4];"
                 : "=r"(r[0]), "=r"(r[1]), "=r"(r[2]), "=r"(r[3]) : "r"(addr));
}
__device__ __forceinline__ void ldsm4t(uint32_t* r, uint32_t addr) {
    asm volatile("ldmatrix.sync.aligned.m8n8.x4.trans.shared.b16 {%0,%1,%2,%3}, [%4];"
                 : "=r"(r[0]), "=r"(r[1]), "=r"(r[2]), "=r"(r[3]) : "r"(addr));
}
__device__ __forceinline__ void mma_tf32(float* c, const uint32_t* a, const uint32_t* b) {
    asm volatile(
        "mma.sync.aligned.m16n8k8.row.col.f32.tf32.tf32.f32 "
        "{%0,%1,%2,%3}, {%4,%5,%6,%7}, {%8,%9}, {%0,%1,%2,%3};"
        : "+f"(c[0]), "+f"(c[1]), "+f"(c[2]), "+f"(c[3])
        : "r"(a[0]), "r"(a[1]), "r"(a[2]), "r"(a[3]), "r"(b[0]), "r"(b[1]));
}
__device__ __forceinline__ void mma_bf16(float* c, const uint32_t* a, const uint32_t* b) {
    asm volatile(
        "mma.sync.aligned.m16n8k16.row.col.f32.bf16.bf16.f32 "
        "{%0,%1,%2,%3}, {%4,%5,%6,%7}, {%8,%9}, {%0,%1,%2,%3};"
        : "+f"(c[0]), "+f"(c[1]), "+f"(c[2]), "+f"(c[3])
        : "r"(a[0]), "r"(a[1]), "r"(a[2]), "r"(a[3]), "r"(b[0]), "r"(b[1]));
}
__device__ __forceinline__ uint32_t f2tf(uint32_t fbits) {
    uint32_t r;
    asm("cvt.rna.tf32.f32 %0, %1;" : "=r"(r) : "f"(__uint_as_float(fbits)));
    return r;
}
__device__ __forceinline__ int4 cvt4(int4 v) {
    int4 o;
    o.x = (int)f2tf((uint32_t)v.x);
    o.y = (int)f2tf((uint32_t)v.y);
    o.z = (int)f2tf((uint32_t)v.z);
    o.w = (int)f2tf((uint32_t)v.w);
    return o;
}
// pack two floats into bf16x2: lo -> low half, hi -> high half
__device__ __forceinline__ uint32_t pkbf2(float lo, float hi) {
    uint32_t r;
    asm("cvt.rn.bf16x2.f32 %0, %1, %2;" : "=r"(r) : "f"(hi), "f"(lo));
    return r;
}

// ---------------------------------------------------------------------------
// Device scratch
// ---------------------------------------------------------------------------
__device__ float g_q[MM * HH * HD];
__device__ float g_k[MM * KVHn * HD];
__device__ float g_v[MM * KVHn * HD];
__device__ float g_att[MM * HH * HD];       // attention output (fp32)
__device__ float g_wt[1536 * DD];           // [wq|wk|wv]^T  (fp32, [N,K])
__device__ float g_wo_t[DD * DD];           // wo^T          (fp32, [N,K])

// ---------------------------------------------------------------------------
// Transpose: W[1024][N] row-major -> T[rowOff+n][k], fp32. 32x32 tile + pad.
// ---------------------------------------------------------------------------
__global__ __launch_bounds__(256) void transpose_kernel(
    const float* __restrict__ W, int N, float* __restrict__ T, int rowOff)
{
    __shared__ float tile[32][33];
    const int tx = threadIdx.x, ty = threadIdx.y;
    const int n0 = blockIdx.x * 32, k0 = blockIdx.y * 32;
    #pragma unroll
    for (int j = ty; j < 32; j += 8)
        tile[j][tx] = W[(k0 + j) * N + n0 + tx];
    __syncthreads();
    #pragma unroll
    for (int j = ty; j < 32; j += 8)
        T[(rowOff + n0 + j) * 1024 + k0 + tx] = tile[tx][j];
}

// ---------------------------------------------------------------------------
// tf32 HMMA GEMM (R10, unchanged): D = A[M,1024] @ B[N,1024]^T.
// ---------------------------------------------------------------------------
__global__ __launch_bounds__(256) void mma_gemm_kernel(
    const float* __restrict__ A, const float* __restrict__ B,
    const float* __restrict__ fc, const float* __restrict__ fs,
    float* __restrict__ outp, int mode)
{
    __shared__ __align__(16) float sA[128 * 36];
    __shared__ __align__(16) float sB[128 * 36];

    const int tid  = threadIdx.x;
    const int lane = tid & 31, wid = tid >> 5;
    const int wm = wid & 1, wn = wid >> 1;
    const int m0 = blockIdx.y * 128, n0 = blockIdx.x * 128;

    const int lr = tid >> 1, lcw = (tid & 1) * 16;
    const float* pA = &A[(m0 + lr) * 1024 + lcw];
    const float* pB = &B[(n0 + lr) * 1024 + lcw];
    const int ss = lr * 36 + lcw;

    const int arow = wm * 64 + (lane & 7) + ((lane & 8) ? 8 : 0);
    const uint32_t a_base = arow * 144 + ((lane & 16) ? 16 : 0);
    const int brow = wn * 32 + (lane & 7) + ((lane & 16) ? 8 : 0);
    const uint32_t b_base = brow * 144 + ((lane & 8) ? 16 : 0);
    const uint32_t uA = smem_u32(sA) + a_base;
    const uint32_t uB = smem_u32(sB) + b_base;

    float acc[4][4][4];
    #pragma unroll
    for (int i = 0; i < 4; i++)
        #pragma unroll
        for (int j = 0; j < 4; j++)
            #pragma unroll
            for (int q = 0; q < 4; q++) acc[i][j][q] = 0.f;

    int4 pr[8];
    #define PREF(koff) do {                                   \
        pr[0] = *(const int4*)&pA[koff];                      \
        pr[1] = *(const int4*)&pA[(koff) + 4];                \
        pr[2] = *(const int4*)&pA[(koff) + 8];                \
        pr[3] = *(const int4*)&pA[(koff) + 12];               \
        pr[4] = *(const int4*)&pB[koff];                      \
        pr[5] = *(const int4*)&pB[(koff) + 4];                \
        pr[6] = *(const int4*)&pB[(koff) + 8];                \
        pr[7] = *(const int4*)&pB[(koff) + 12];               \
    } while (0)

    PREF(0);
    for (int kc = 0; kc < 32; ++kc) {
        if (kc) __syncthreads();
        *(int4*)&sA[ss]      = cvt4(pr[0]);
        *(int4*)&sA[ss + 4]  = cvt4(pr[1]);
        *(int4*)&sA[ss + 8]  = cvt4(pr[2]);
        *(int4*)&sA[ss + 12] = cvt4(pr[3]);
        *(int4*)&sB[ss]      = cvt4(pr[4]);
        *(int4*)&sB[ss + 4]  = cvt4(pr[5]);
        *(int4*)&sB[ss + 8]  = cvt4(pr[6]);
        *(int4*)&sB[ss + 12] = cvt4(pr[7]);
        __syncthreads();
        if (kc < 31) PREF((kc + 1) * 32);

        #pragma unroll
        for (int ks = 0; ks < 4; ++ks) {
            const uint32_t kb = ks * 32;
            uint32_t Af[4][4], Bf[4][2];
            #pragma unroll
            for (int mt = 0; mt < 4; mt++)
                ldsm4(Af[mt], uA + mt * 16 * 144 + kb);
            #pragma unroll
            for (int np = 0; np < 2; np++) {
                uint32_t t[4];
                ldsm4(t, uB + np * 16 * 144 + kb);
                Bf[2*np][0]   = t[0]; Bf[2*np][1]   = t[1];
                Bf[2*np+1][0] = t[2]; Bf[2*np+1][1] = t[3];
            }
            #pragma unroll
            for (int mt = 0; mt < 4; mt++)
                #pragma unroll
                for (int nt = 0; nt < 4; nt++)
                    mma_tf32(acc[mt][nt], Af[mt], Bf[nt]);
        }
    }

    const int g = lane >> 2, t2 = (lane & 3) * 2;
    float* dst; int ld, coff; bool rope;
    if (mode == 1)      { dst = outp;  ld = 1024; coff = n0;        rope = false; }
    else if (n0 < 1024) { dst = g_q;   ld = 1024; coff = n0;        rope = true;  }
    else if (n0 < 1280) { dst = g_k;   ld = 256;  coff = n0 - 1024; rope = true;  }
    else                { dst = g_v;   ld = 256;  coff = n0 - 1280; rope = false; }

    #pragma unroll
    for (int mt = 0; mt < 4; mt++) {
        #pragma unroll
        for (int h2 = 0; h2 < 2; h2++) {
            const int row = m0 + wm * 64 + mt * 16 + g + h2 * 8;
            const int s   = row & (SS - 1);
            #pragma unroll
            for (int nt = 0; nt < 4; nt++) {
                const int col = wn * 32 + nt * 8 + t2;
                float v0 = acc[mt][nt][h2 * 2];
                float v1 = acc[mt][nt][h2 * 2 + 1];
                if (rope) {
                    const int j = ((n0 + col) & 63) >> 1;
                    float c  = fc[s * 32 + j];
                    float sn = fs[s * 32 + j];
                    float o0 = v0 * c  - v1 * sn;
                    float o1 = v0 * sn + v1 * c;
                    v0 = o0; v1 = o1;
                }
                *(float2*)&dst[row * ld + coff + col] = make_float2(v0, v1);
            }
        }
    }
}

// ---------------------------------------------------------------------------
// Tensor-core sliding-window attention (single-pass softmax).
// Block = (b, kvh, 16 queries). M = 64 rows (16q x 4 rep-heads),
// N = 80 keys [qbase-64, qbase+16), K-dim = 64.
// S = Q@K^T on tf32 MMA (Q frags from gmem, K tf32 in smem).
// Softmax in registers (4-lane shfl row reductions, window mask -> -1e30).
// P@V on bf16 MMA, hi/lo split of BOTH P and V (3 MMAs, ~1e-4 error).
// Warp owns 16 rows x all 80 cols, so P stays in registers (C->A identity).
// ---------------------------------------------------------------------------
__global__ __launch_bounds__(128) void attn_kernel()
{
    __shared__ __align__(16) float Ks[80 * 68];            // tf32 [key][d]
    __shared__ __align__(16) __nv_bfloat16 Vh[80 * 72];    // bf16 hi [key][d]
    __shared__ __align__(16) __nv_bfloat16 Vl[80 * 72];    // bf16 lo
    const int b   = blockIdx.z;
    const int kvh = blockIdx.y;
    const int qbase  = blockIdx.x * 16;
    const int kstart = qbase - WIN;            // may be negative
    const int tid = threadIdx.x;
    const int lane = tid & 31, w = tid >> 5;

    // ---- stage K (tf32) and V (bf16 hi/lo); zero-fill key < 0 ----
    for (int i = tid; i < 80 * 16; i += 128) {
        const int row = i >> 4, c4 = (i & 15) * 4;
        const int key = kstart + row;
        float4 kv, vv;
        if (key >= 0) {
            const int gidx = ((b * SS + key) * KVHn + kvh) * 64 + c4;
            kv = *(const float4*)&g_k[gidx];
            vv = *(const float4*)&g_v[gidx];
        } else {
            kv = make_float4(0.f, 0.f, 0.f, 0.f);
            vv = make_float4(0.f, 0.f, 0.f, 0.f);
        }
        int4 kt;
        kt.x = (int)f2tf(__float_as_uint(kv.x));
        kt.y = (int)f2tf(__float_as_uint(kv.y));
        kt.z = (int)f2tf(__float_as_uint(kv.z));
        kt.w = (int)f2tf(__float_as_uint(kv.w));
        *(int4*)&Ks[row * 68 + c4] = kt;
        float h0 = __bfloat162float(__float2bfloat16(vv.x));
        float h1 = __bfloat162float(__float2bfloat16(vv.y));
        float h2 = __bfloat162float(__float2bfloat16(vv.z));
        float h3 = __bfloat162float(__float2bfloat16(vv.w));
        uint2 hp, lp;
        hp.x = pkbf2(h0, h1);              hp.y = pkbf2(h2, h3);
        lp.x = pkbf2(vv.x - h0, vv.y - h1); lp.y = pkbf2(vv.z - h2, vv.w - h3);
        *(uint2*)&Vh[row * 72 + c4] = hp;
        *(uint2*)&Vl[row * 72 + c4] = lp;
    }
    __syncthreads();

    // ---- S = Q @ K^T : warp w owns M-rows [16w, 16w+16), all 80 cols ----
    const int r  = lane >> 2, cA = lane & 3;
    const int mr0 = 16 * w + r;            // row g
    const int mr1 = mr0 + 8;               // row g+8
    const int qg0 = qbase + (mr0 >> 2), h0i = kvh * 4 + (mr0 & 3);
    const int qg1 = qbase + (mr1 >> 2), h1i = kvh * 4 + (mr1 & 3);
    const float* qp0 = &g_q[((b * SS + qg0) * HH + h0i) * 64];
    const float* qp1 = &g_q[((b * SS + qg1) * HH + h1i) * 64];

    const int brow = (lane & 7) + ((lane & 16) ? 8 : 0);
    const uint32_t bbase = smem_u32(Ks) + brow * 272 + ((lane & 8) ? 16 : 0);

    float sc[10][4];
    #pragma unroll
    for (int t = 0; t < 10; t++)
        #pragma unroll
        for (int q = 0; q < 4; q++) sc[t][q] = 0.f;

    #pragma unroll
    for (int k8 = 0; k8 < 8; k8++) {
        uint32_t a[4];
        a[0] = f2tf(__float_as_uint(qp0[k8 * 8 + cA]));
        a[1] = f2tf(__float_as_uint(qp1[k8 * 8 + cA]));
        a[2] = f2tf(__float_as_uint(qp0[k8 * 8 + cA + 4]));
        a[3] = f2tf(__float_as_uint(qp1[k8 * 8 + cA + 4]));
        #pragma unroll
        for (int np = 0; np < 5; np++) {
            uint32_t t[4];
            ldsm4(t, bbase + np * 16 * 272 + k8 * 32);
            uint32_t b0[2] = {t[0], t[1]}, b1[2] = {t[2], t[3]};
            mma_tf32(sc[2 * np],     a, b0);
            mma_tf32(sc[2 * np + 1], a, b1);
        }
    }

    // ---- masked softmax over rows (4-lane shfl reductions) ----
    const int qiA = mr0 >> 2, qiB = mr1 >> 2;   // relative query idx 0..15
    const int jlo = (kstart < 0) ? -kstart : 0;
    const int jmin0 = (qiA > jlo) ? qiA : jlo, jmax0 = qiA + WIN;
    const int jmin1 = (qiB > jlo) ? qiB : jlo, jmax1 = qiB + WIN;
    float mx0 = -1e30f, mx1 = -1e30f;
    #pragma unroll
    for (int t = 0; t < 10; t++) {
        const int jb = 8 * t + 2 * cA;
        #pragma unroll
        for (int e = 0; e < 2; e++) {
            const int j = jb + e;
            float v0 = sc[t][e]     * 0.125f;
            float v1 = sc[t][2 + e] * 0.125f;
            v0 = (j >= jmin0 && j <= jmax0) ? v0 : -1e30f;
            v1 = (j >= jmin1 && j <= jmax1) ? v1 : -1e30f;
            sc[t][e] = v0; sc[t][2 + e] = v1;
            mx0 = fmaxf(mx0, v0); mx1 = fmaxf(mx1, v1);
        }
    }
    mx0 = fmaxf(mx0, __shfl_xor_sync(0xffffffffu, mx0, 1));
    mx0 = fmaxf(mx0, __shfl_xor_sync(0xffffffffu, mx0, 2));
    mx1 = fmaxf(mx1, __shfl_xor_sync(0xffffffffu, mx1, 1));
    mx1 = fmaxf(mx1, __shfl_xor_sync(0xffffffffu, mx1, 2));
    float sm0 = 0.f, sm1 = 0.f;
    #pragma unroll
    for (int t = 0; t < 10; t++) {
        #pragma unroll
        for (int e = 0; e < 2; e++) {
            float p0 = __expf(sc[t][e]     - mx0);
            float p1 = __expf(sc[t][2 + e] - mx1);
            sc[t][e] = p0; sc[t][2 + e] = p1;
            sm0 += p0; sm1 += p1;
        }
    }
    sm0 += __shfl_xor_sync(0xffffffffu, sm0, 1);
    sm0 += __shfl_xor_sync(0xffffffffu, sm0, 2);
    sm1 += __shfl_xor_sync(0xffffffffu, sm1, 1);
    sm1 += __shfl_xor_sync(0xffffffffu, sm1, 2);
    const float inv0 = 1.f / sm0, inv1 = 1.f / sm1;

    // ---- convert P -> bf16 hi/lo A-fragments (in registers) ----
    uint32_t Ph[5][4], Pl[5][4];
    #pragma unroll
    for (int kk = 0; kk < 5; kk++) {
        #pragma unroll
        for (int half = 0; half < 2; half++) {      // tile 2kk, 2kk+1
            const int t = 2 * kk + half;
            float p00 = sc[t][0], p01 = sc[t][1];   // row g
            float p10 = sc[t][2], p11 = sc[t][3];   // row g+8
            float h00 = __bfloat162float(__float2bfloat16(p00));
            float h01 = __bfloat162float(__float2bfloat16(p01));
            float h10 = __bfloat162float(__float2bfloat16(p10));
            float h11 = __bfloat162float(__float2bfloat16(p11));
            Ph[kk][half * 2]     = pkbf2(h00, h01);
            Ph[kk][half * 2 + 1] = pkbf2(h10, h11);
            Pl[kk][half * 2]     = pkbf2(p00 - h00, p01 - h01);
            Pl[kk][half * 2 + 1] = pkbf2(p10 - h10, p11 - h11);
        }
    }
    // reorder: m16n8k16 A frag = {a0=(g,k0pair), a1=(g+8,k0pair), a2=(g,k8pair), a3=(g+8,k8pair)}
    // currently Ph[kk] = {tile2kk row g, tile2kk row g+8, tile2kk+1 row g, tile2kk+1 row g+8}
    // which is exactly {a0, a1, a2, a3}.  (tile 2kk = k cols [0,8), tile 2kk+1 = [8,16))

    // ---- O = P @ V (bf16 hi/lo, 3 MMAs per tile) ----
    float oc[8][4];
    #pragma unroll
    for (int i = 0; i < 8; i++)
        #pragma unroll
        for (int q = 0; q < 4; q++) oc[i][q] = 0.f;

    const uint32_t vbase = (lane & 15) * 144 + 16 * (lane >> 4);
    const uint32_t uVh = smem_u32(Vh) + vbase;
    const uint32_t uVl = smem_u32(Vl) + vbase;
    #pragma unroll
    for (int kk = 0; kk < 5; kk++) {
        #pragma unroll
        for (int nn = 0; nn < 4; nn++) {          // n16 chunks of 64 dims
            uint32_t th[4], tl[4];
            ldsm4t(th, uVh + kk * 2304 + nn * 32);
            ldsm4t(tl, uVl + kk * 2304 + nn * 32);
            uint32_t bh0[2] = {th[0], th[1]}, bh1[2] = {th[2], th[3]};
            uint32_t bl0[2] = {tl[0], tl[1]}, bl1[2] = {tl[2], tl[3]};
            mma_bf16(oc[2 * nn],     Ph[kk], bh0);   // Ph*Vh
            mma_bf16(oc[2 * nn + 1], Ph[kk], bh1);
            mma_bf16(oc[2 * nn],     Ph[kk], bl0);   // Ph*Vl
            mma_bf16(oc[2 * nn + 1], Ph[kk], bl1);
            mma_bf16(oc[2 * nn],     Pl[kk], bh0);   // Pl*Vh
            mma_bf16(oc[2 * nn + 1], Pl[kk], bh1);
        }
    }

    // ---- epilogue: rows mr0/mr1, cols 8nt + 2cA ----
    float* o0 = &g_att[(b * SS + qg0) * 1024 + h0i * 64];
    float* o1 = &g_att[(b * SS + qg1) * 1024 + h1i * 64];
    #pragma unroll
    for (int nt = 0; nt < 8; nt++) {
        const int col = 8 * nt + 2 * cA;
        *(float2*)&o0[col] = make_float2(oc[nt][0] * inv0, oc[nt][1] * inv0);
        *(float2*)&o1[col] = make_float2(oc[nt][2] * inv1, oc[nt][3] * inv1);
    }
}

// ---------------------------------------------------------------------------
extern "C" void kernel_launch(void* const* d_in, const int* in_sizes, int n_in,
                              void* d_out, int out_size)
{
    const float* x  = (const float*)d_in[0];
    const float* fc = (const float*)d_in[1];
    const float* fs = (const float*)d_in[2];
    const float* wq = (const float*)d_in[3];
    const float* wk = (const float*)d_in[4];
    const float* wv = (const float*)d_in[5];
    const float* wo = (const float*)d_in[6];
    float* out = (float*)d_out;

    float *wt, *wot, *att;
    cudaGetSymbolAddress((void**)&wt,  g_wt);
    cudaGetSymbolAddress((void**)&wot, g_wo_t);
    cudaGetSymbolAddress((void**)&att, g_att);

    transpose_kernel<<<dim3(32, 32), dim3(32, 8)>>>(wq, 1024, wt, 0);
    transpose_kernel<<<dim3(8, 32),  dim3(32, 8)>>>(wk, 256,  wt, 1024);
    transpose_kernel<<<dim3(8, 32),  dim3(32, 8)>>>(wv, 256,  wt, 1280);
    transpose_kernel<<<dim3(32, 32), dim3(32, 8)>>>(wo, 1024, wot, 0);

    // QKV projection + RoPE (tf32 HMMA)
    mma_gemm_kernel<<<dim3(12, 32), 256>>>(x, wt, fc, fs, nullptr, 0);
    // tensor-core attention
    attn_kernel<<<dim3(SS / 16, KVHn, BB), 128>>>();
    // output projection (tf32 HMMA)
    mma_gemm_kernel<<<dim3(8, 32), 256>>>(att, wot, nullptr, nullptr, out, 1);
}

// round 13
// speedup vs baseline: 1.8265x; 1.0251x over previous
#include <cuda_runtime.h>
#include <cuda_bf16.h>
#include <cstdint>

#define BB   2
#define SS   2048
#define DD   1024
#define HH   16
#define KVHn 4
#define HD   64
#define WIN  64
#define MM   (BB*SS)   // 4096

typedef unsigned long long ull;

__device__ __forceinline__ uint32_t smem_u32(const void* p) {
    uint32_t a;
    asm("{ .reg .u64 t; cvta.to.shared.u64 t, %1; cvt.u32.u64 %0, t; }"
        : "=r"(a) : "l"(p));
    return a;
}

// warp-level tensor core ops (plain sm_80+ ISA, no arch suffix)
__device__ __forceinline__ void ldsm4(uint32_t* r, uint32_t addr) {
    asm volatile("ldmatrix.sync.aligned.m8n8.x4.shared.b16 {%0,%1,%2,%3}, [%4];"
                 : "=r"(r[0]), "=r"(r[1]), "=r"(r[2]), "=r"(r[3]) : "r"(addr));
}
__device__ __forceinline__ void mma_tf32(float* c, const uint32_t* a, const uint32_t* b) {
    asm volatile(
        "mma.sync.aligned.m16n8k8.row.col.f32.tf32.tf32.f32 "
        "{%0,%1,%2,%3}, {%4,%5,%6,%7}, {%8,%9}, {%0,%1,%2,%3};"
        : "+f"(c[0]), "+f"(c[1]), "+f"(c[2]), "+f"(c[3])
        : "r"(a[0]), "r"(a[1]), "r"(a[2]), "r"(a[3]), "r"(b[0]), "r"(b[1]));
}
__device__ __forceinline__ uint32_t f2tf(uint32_t fbits) {
    uint32_t r;
    asm("cvt.rna.tf32.f32 %0, %1;" : "=r"(r) : "f"(__uint_as_float(fbits)));
    return r;
}
__device__ __forceinline__ int4 cvt4(int4 v) {
    int4 o;
    o.x = (int)f2tf((uint32_t)v.x);
    o.y = (int)f2tf((uint32_t)v.y);
    o.z = (int)f2tf((uint32_t)v.z);
    o.w = (int)f2tf((uint32_t)v.w);
    return o;
}

// ---------------------------------------------------------------------------
// Device scratch
// ---------------------------------------------------------------------------
__device__ float g_q[MM * HH * HD];
__device__ float g_k[MM * KVHn * HD];
__device__ float g_v[MM * KVHn * HD];
__device__ float g_att[MM * HH * HD];       // attention output (fp32)
__device__ float g_wt[1536 * DD];           // [wq|wk|wv]^T  (fp32, [N,K])
__device__ float g_wo_t[DD * DD];           // wo^T          (fp32, [N,K])

// ---------------------------------------------------------------------------
// Fused transpose of all 4 weight matrices in ONE launch (they were 4
// serialized ~6us kernels). x-tile 0-31: wq, 32-39: wk, 40-47: wv, 48-79: wo.
// ---------------------------------------------------------------------------
__global__ __launch_bounds__(256) void transpose_all_kernel(
    const float* __restrict__ wq, const float* __restrict__ wk,
    const float* __restrict__ wv, const float* __restrict__ wo,
    float* __restrict__ wt, float* __restrict__ wot)
{
    __shared__ float tile[32][33];
    int bx = blockIdx.x;
    const float* W; float* T; int N, rowOff;
    if (bx < 32)      { W = wq; T = wt;  N = 1024; rowOff = 0;    }
    else if (bx < 40) { W = wk; T = wt;  N = 256;  rowOff = 1024; bx -= 32; }
    else if (bx < 48) { W = wv; T = wt;  N = 256;  rowOff = 1280; bx -= 40; }
    else              { W = wo; T = wot; N = 1024; rowOff = 0;    bx -= 48; }
    const int tx = threadIdx.x, ty = threadIdx.y;
    const int n0 = bx * 32, k0 = blockIdx.y * 32;
    #pragma unroll
    for (int j = ty; j < 32; j += 8)
        tile[j][tx] = W[(k0 + j) * N + n0 + tx];
    __syncthreads();
    #pragma unroll
    for (int j = ty; j < 32; j += 8)
        T[(rowOff + n0 + j) * 1024 + k0 + tx] = tile[tx][j];
}

// ---------------------------------------------------------------------------
// tf32 HMMA GEMM (R10, unchanged): D = A[M,1024] @ B[N,1024]^T.
// ---------------------------------------------------------------------------
__global__ __launch_bounds__(256) void mma_gemm_kernel(
    const float* __restrict__ A, const float* __restrict__ B,
    const float* __restrict__ fc, const float* __restrict__ fs,
    float* __restrict__ outp, int mode)
{
    __shared__ __align__(16) float sA[128 * 36];
    __shared__ __align__(16) float sB[128 * 36];

    const int tid  = threadIdx.x;
    const int lane = tid & 31, wid = tid >> 5;
    const int wm = wid & 1, wn = wid >> 1;
    const int m0 = blockIdx.y * 128, n0 = blockIdx.x * 128;

    const int lr = tid >> 1, lcw = (tid & 1) * 16;
    const float* pA = &A[(m0 + lr) * 1024 + lcw];
    const float* pB = &B[(n0 + lr) * 1024 + lcw];
    const int ss = lr * 36 + lcw;

    const int arow = wm * 64 + (lane & 7) + ((lane & 8) ? 8 : 0);
    const uint32_t a_base = arow * 144 + ((lane & 16) ? 16 : 0);
    const int brow = wn * 32 + (lane & 7) + ((lane & 16) ? 8 : 0);
    const uint32_t b_base = brow * 144 + ((lane & 8) ? 16 : 0);
    const uint32_t uA = smem_u32(sA) + a_base;
    const uint32_t uB = smem_u32(sB) + b_base;

    float acc[4][4][4];
    #pragma unroll
    for (int i = 0; i < 4; i++)
        #pragma unroll
        for (int j = 0; j < 4; j++)
            #pragma unroll
            for (int q = 0; q < 4; q++) acc[i][j][q] = 0.f;

    int4 pr[8];
    #define PREF(koff) do {                                   \
        pr[0] = *(const int4*)&pA[koff];                      \
        pr[1] = *(const int4*)&pA[(koff) + 4];                \
        pr[2] = *(const int4*)&pA[(koff) + 8];                \
        pr[3] = *(const int4*)&pA[(koff) + 12];               \
        pr[4] = *(const int4*)&pB[koff];                      \
        pr[5] = *(const int4*)&pB[(koff) + 4];                \
        pr[6] = *(const int4*)&pB[(koff) + 8];                \
        pr[7] = *(const int4*)&pB[(koff) + 12];               \
    } while (0)

    PREF(0);
    for (int kc = 0; kc < 32; ++kc) {
        if (kc) __syncthreads();
        *(int4*)&sA[ss]      = cvt4(pr[0]);
        *(int4*)&sA[ss + 4]  = cvt4(pr[1]);
        *(int4*)&sA[ss + 8]  = cvt4(pr[2]);
        *(int4*)&sA[ss + 12] = cvt4(pr[3]);
        *(int4*)&sB[ss]      = cvt4(pr[4]);
        *(int4*)&sB[ss + 4]  = cvt4(pr[5]);
        *(int4*)&sB[ss + 8]  = cvt4(pr[6]);
        *(int4*)&sB[ss + 12] = cvt4(pr[7]);
        __syncthreads();
        if (kc < 31) PREF((kc + 1) * 32);

        #pragma unroll
        for (int ks = 0; ks < 4; ++ks) {
            const uint32_t kb = ks * 32;
            uint32_t Af[4][4], Bf[4][2];
            #pragma unroll
            for (int mt = 0; mt < 4; mt++)
                ldsm4(Af[mt], uA + mt * 16 * 144 + kb);
            #pragma unroll
            for (int np = 0; np < 2; np++) {
                uint32_t t[4];
                ldsm4(t, uB + np * 16 * 144 + kb);
                Bf[2*np][0]   = t[0]; Bf[2*np][1]   = t[1];
                Bf[2*np+1][0] = t[2]; Bf[2*np+1][1] = t[3];
            }
            #pragma unroll
            for (int mt = 0; mt < 4; mt++)
                #pragma unroll
                for (int nt = 0; nt < 4; nt++)
                    mma_tf32(acc[mt][nt], Af[mt], Bf[nt]);
        }
    }

    const int g = lane >> 2, t2 = (lane & 3) * 2;
    float* dst; int ld, coff; bool rope;
    if (mode == 1)      { dst = outp;  ld = 1024; coff = n0;        rope = false; }
    else if (n0 < 1024) { dst = g_q;   ld = 1024; coff = n0;        rope = true;  }
    else if (n0 < 1280) { dst = g_k;   ld = 256;  coff = n0 - 1024; rope = true;  }
    else                { dst = g_v;   ld = 256;  coff = n0 - 1280; rope = false; }

    #pragma unroll
    for (int mt = 0; mt < 4; mt++) {
        #pragma unroll
        for (int h2 = 0; h2 < 2; h2++) {
            const int row = m0 + wm * 64 + mt * 16 + g + h2 * 8;
            const int s   = row & (SS - 1);
            #pragma unroll
            for (int nt = 0; nt < 4; nt++) {
                const int col = wn * 32 + nt * 8 + t2;
                float v0 = acc[mt][nt][h2 * 2];
                float v1 = acc[mt][nt][h2 * 2 + 1];
                if (rope) {
                    const int j = ((n0 + col) & 63) >> 1;
                    float c  = fc[s * 32 + j];
                    float sn = fs[s * 32 + j];
                    float o0 = v0 * c  - v1 * sn;
                    float o1 = v0 * sn + v1 * c;
                    v0 = o0; v1 = o1;
                }
                *(float2*)&dst[row * ld + coff + col] = make_float2(v0, v1);
            }
        }
    }
}

// ---------------------------------------------------------------------------
// Tensor-core sliding-window attention, all-tf32 (single-pass softmax).
// Block = (b, kvh, 16 queries). M = 64 rows (16q x 4 rep-heads),
// N = 80 keys [qbase-64, qbase+16), K-dim = 64.
// S = Q@K^T on tf32 MMA (Q frags from gmem, K tf32 in smem [key][d]).
// Softmax in registers (4-lane shfl reductions, window mask -> -1e30).
// P tf32-rounded into the DEAD K smem region ([row][key], stride 84,
// warp-private rows), then P@V on tf32 MMA with V staged transposed
// [d][key] tf32 -- reuses the GEMM's proven ldmatrix A/B addressing.
// ---------------------------------------------------------------------------
__global__ __launch_bounds__(128) void attn_kernel()
{
    __shared__ __align__(16) float Ks[80 * 68];   // K tf32 [key][d]; later P [row][key] (stride 84)
    __shared__ __align__(16) float Vs[64 * 84];   // V tf32 [d][key]
    const int b   = blockIdx.z;
    const int kvh = blockIdx.y;
    const int qbase  = blockIdx.x * 16;
    const int kstart = qbase - WIN;            // may be negative
    const int tid = threadIdx.x;
    const int lane = tid & 31, w = tid >> 5;

    // ---- stage K [key][d] tf32; V transposed [d][key] tf32; zero key<0 ----
    uint32_t* Vw = (uint32_t*)Vs;
    for (int i = tid; i < 80 * 16; i += 128) {
        const int row = i >> 4, c4 = (i & 15) * 4;
        const int key = kstart + row;
        float4 kv, vv;
        if (key >= 0) {
            const int gidx = ((b * SS + key) * KVHn + kvh) * 64 + c4;
            kv = *(const float4*)&g_k[gidx];
            vv = *(const float4*)&g_v[gidx];
        } else {
            kv = make_float4(0.f, 0.f, 0.f, 0.f);
            vv = kv;
        }
        int4 kt;
        kt.x = (int)f2tf(__float_as_uint(kv.x));
        kt.y = (int)f2tf(__float_as_uint(kv.y));
        kt.z = (int)f2tf(__float_as_uint(kv.z));
        kt.w = (int)f2tf(__float_as_uint(kv.w));
        *(int4*)&Ks[row * 68 + c4] = kt;
        Vw[(c4 + 0) * 84 + row] = f2tf(__float_as_uint(vv.x));
        Vw[(c4 + 1) * 84 + row] = f2tf(__float_as_uint(vv.y));
        Vw[(c4 + 2) * 84 + row] = f2tf(__float_as_uint(vv.z));
        Vw[(c4 + 3) * 84 + row] = f2tf(__float_as_uint(vv.w));
    }
    __syncthreads();

    // ---- S = Q @ K^T : warp w owns M-rows [16w, 16w+16), all 80 cols ----
    const int r  = lane >> 2, cA = lane & 3;
    const int mr0 = 16 * w + r;            // row g
    const int mr1 = mr0 + 8;               // row g+8
    const int qg0 = qbase + (mr0 >> 2), h0i = kvh * 4 + (mr0 & 3);
    const int qg1 = qbase + (mr1 >> 2), h1i = kvh * 4 + (mr1 & 3);
    const float* qp0 = &g_q[((b * SS + qg0) * HH + h0i) * 64];
    const float* qp1 = &g_q[((b * SS + qg1) * HH + h1i) * 64];

    const int brow = (lane & 7) + ((lane & 16) ? 8 : 0);
    const uint32_t bbase = smem_u32(Ks) + brow * 272 + ((lane & 8) ? 16 : 0);

    float sc[10][4];
    #pragma unroll
    for (int t = 0; t < 10; t++)
        #pragma unroll
        for (int q = 0; q < 4; q++) sc[t][q] = 0.f;

    #pragma unroll
    for (int k8 = 0; k8 < 8; k8++) {
        uint32_t a[4];
        a[0] = f2tf(__float_as_uint(qp0[k8 * 8 + cA]));
        a[1] = f2tf(__float_as_uint(qp1[k8 * 8 + cA]));
        a[2] = f2tf(__float_as_uint(qp0[k8 * 8 + cA + 4]));
        a[3] = f2tf(__float_as_uint(qp1[k8 * 8 + cA + 4]));
        #pragma unroll
        for (int np = 0; np < 5; np++) {
            uint32_t t[4];
            ldsm4(t, bbase + np * 16 * 272 + k8 * 32);
            uint32_t b0[2] = {t[0], t[1]}, b1[2] = {t[2], t[3]};
            mma_tf32(sc[2 * np],     a, b0);
            mma_tf32(sc[2 * np + 1], a, b1);
        }
    }

    // ---- masked softmax over rows (4-lane shfl reductions) ----
    const int qiA = mr0 >> 2, qiB = mr1 >> 2;   // relative query idx 0..15
    const int jlo = (kstart < 0) ? -kstart : 0;
    const int jmin0 = (qiA > jlo) ? qiA : jlo, jmax0 = qiA + WIN;
    const int jmin1 = (qiB > jlo) ? qiB : jlo, jmax1 = qiB + WIN;
    float mx0 = -1e30f, mx1 = -1e30f;
    #pragma unroll
    for (int t = 0; t < 10; t++) {
        const int jb = 8 * t + 2 * cA;
        #pragma unroll
        for (int e = 0; e < 2; e++) {
            const int j = jb + e;
            float v0 = sc[t][e]     * 0.125f;
            float v1 = sc[t][2 + e] * 0.125f;
            v0 = (j >= jmin0 && j <= jmax0) ? v0 : -1e30f;
            v1 = (j >= jmin1 && j <= jmax1) ? v1 : -1e30f;
            sc[t][e] = v0; sc[t][2 + e] = v1;
            mx0 = fmaxf(mx0, v0); mx1 = fmaxf(mx1, v1);
        }
    }
    mx0 = fmaxf(mx0, __shfl_xor_sync(0xffffffffu, mx0, 1));
    mx0 = fmaxf(mx0, __shfl_xor_sync(0xffffffffu, mx0, 2));
    mx1 = fmaxf(mx1, __shfl_xor_sync(0xffffffffu, mx1, 1));
    mx1 = fmaxf(mx1, __shfl_xor_sync(0xffffffffu, mx1, 2));
    float sm0 = 0.f, sm1 = 0.f;
    #pragma unroll
    for (int t = 0; t < 10; t++) {
        #pragma unroll
        for (int e = 0; e < 2; e++) {
            float p0 = __expf(sc[t][e]     - mx0);
            float p1 = __expf(sc[t][2 + e] - mx1);
            sc[t][e] = p0; sc[t][2 + e] = p1;
            sm0 += p0; sm1 += p1;
        }
    }
    sm0 += __shfl_xor_sync(0xffffffffu, sm0, 1);
    sm0 += __shfl_xor_sync(0xffffffffu, sm0, 2);
    sm1 += __shfl_xor_sync(0xffffffffu, sm1, 1);
    sm1 += __shfl_xor_sync(0xffffffffu, sm1, 2);
    const float inv0 = 1.f / sm0, inv1 = 1.f / sm1;

    // ---- all warps done reading K; recycle Ks as P [64 rows][84 stride] ----
    __syncthreads();
    uint32_t* Ps = (uint32_t*)Ks;
    #pragma unroll
    for (int t = 0; t < 10; t++) {
        const int jb = 8 * t + 2 * cA;
        Ps[mr0 * 84 + jb]     = f2tf(__float_as_uint(sc[t][0]));
        Ps[mr0 * 84 + jb + 1] = f2tf(__float_as_uint(sc[t][1]));
        Ps[mr1 * 84 + jb]     = f2tf(__float_as_uint(sc[t][2]));
        Ps[mr1 * 84 + jb + 1] = f2tf(__float_as_uint(sc[t][3]));
    }
    __syncwarp();   // warp-private rows: only intra-warp visibility needed

    // ---- O = P @ V : tf32 MMA, A from Ps (stride 336B), B from Vs ----
    float oc[8][4];
    #pragma unroll
    for (int i = 0; i < 8; i++)
        #pragma unroll
        for (int q = 0; q < 4; q++) oc[i][q] = 0.f;

    const uint32_t aoff = smem_u32(Ks)
        + (16 * w + (lane & 7) + ((lane & 8) ? 8 : 0)) * 336 + ((lane & 16) ? 16 : 0);
    const uint32_t boff = smem_u32(Vs)
        + ((lane & 7) + ((lane & 16) ? 8 : 0)) * 336 + ((lane & 8) ? 16 : 0);
    #pragma unroll
    for (int k8 = 0; k8 < 10; k8++) {
        uint32_t Af[4];
        ldsm4(Af, aoff + k8 * 32);
        #pragma unroll
        for (int dd = 0; dd < 4; dd++) {
            uint32_t t[4];
            ldsm4(t, boff + dd * 16 * 336 + k8 * 32);
            uint32_t b0[2] = {t[0], t[1]}, b1[2] = {t[2], t[3]};
            mma_tf32(oc[2 * dd],     Af, b0);
            mma_tf32(oc[2 * dd + 1], Af, b1);
        }
    }

    // ---- epilogue: rows mr0/mr1, cols 8nt + 2cA ----
    float* o0 = &g_att[(b * SS + qg0) * 1024 + h0i * 64];
    float* o1 = &g_att[(b * SS + qg1) * 1024 + h1i * 64];
    #pragma unroll
    for (int nt = 0; nt < 8; nt++) {
        const int col = 8 * nt + 2 * cA;
        *(float2*)&o0[col] = make_float2(oc[nt][0] * inv0, oc[nt][1] * inv0);
        *(float2*)&o1[col] = make_float2(oc[nt][2] * inv1, oc[nt][3] * inv1);
    }
}

// ---------------------------------------------------------------------------
extern "C" void kernel_launch(void* const* d_in, const int* in_sizes, int n_in,
                              void* d_out, int out_size)
{
    const float* x  = (const float*)d_in[0];
    const float* fc = (const float*)d_in[1];
    const float* fs = (const float*)d_in[2];
    const float* wq = (const float*)d_in[3];
    const float* wk = (const float*)d_in[4];
    const float* wv = (const float*)d_in[5];
    const float* wo = (const float*)d_in[6];
    float* out = (float*)d_out;

    float *wt, *wot, *att;
    cudaGetSymbolAddress((void**)&wt,  g_wt);
    cudaGetSymbolAddress((void**)&wot, g_wo_t);
    cudaGetSymbolAddress((void**)&att, g_att);

    // all 4 weight transposes in one launch
    transpose_all_kernel<<<dim3(80, 32), dim3(32, 8)>>>(wq, wk, wv, wo, wt, wot);

    // QKV projection + RoPE (tf32 HMMA)
    mma_gemm_kernel<<<dim3(12, 32), 256>>>(x, wt, fc, fs, nullptr, 0);
    // tensor-core attention (all tf32)
    attn_kernel<<<dim3(SS / 16, KVHn, BB), 128>>>();
    // output projection (tf32 HMMA)
    mma_gemm_kernel<<<dim3(8, 32), 256>>>(att, wot, nullptr, nullptr, out, 1);
}